// round 5
// baseline (speedup 1.0000x reference)
#include <cuda_runtime.h>
#include <math.h>

#define NN 512
#define CS 1024
#define CZd 128
#define Hh 12
#define HDd 16
#define PQp 4
#define PVp 8

// ---------------- scratch (device globals; no allocation allowed) ----------
__device__ __align__(16) float g_q[NN * Hh * HDd];          // [i][h*16+d]
__device__ __align__(16) float g_kv[NN * 2 * Hh * HDd];     // [i][h*32 + x]
__device__ __align__(16) float g_qpl[NN * Hh * PQp * 3];    // local q pts (GEMM layout)
__device__ __align__(16) float g_kvpl[NN * Hh * 12 * 3];    // local kv pts
__device__ __align__(16) float g_qpts[NN * Hh * PQp * 3];   // [i][h*12 + p*3 + c] world
__device__ __align__(16) float g_kpts[NN * Hh * PQp * 3];   // [i][h*12 + p*3 + c] world
__device__ __align__(16) float g_vcat[Hh * NN * 40];        // [h][j][0:16 v | 16:40 vpts world]
__device__ __align__(16) float g_a[Hh * NN * NN];           // logits / attn
__device__ __align__(16) float g_o1[Hh * NN * 40];          // a @ vcat
__device__ __align__(16) float g_cat[NN * 2112];            // concat buffer

// ---------------- generic tiled SGEMM: C = A(MxK) @ B(KxNw) (+bias) --------
// BM=BN=64, BK=16, 256 threads, 4x4 per thread. K % 16 == 0, M % 64 == 0.
template <bool HAS_BIAS>
__global__ void gemm_kernel(const float* __restrict__ A, const float* __restrict__ Bm,
                            const float* __restrict__ bias, float* __restrict__ C,
                            int M, int K, int Nw, long sA, long sB, long sC) {
    A += blockIdx.z * sA;
    Bm += blockIdx.z * sB;
    C += blockIdx.z * sC;

    __shared__ __align__(16) float As[16][64];
    __shared__ __align__(16) float Bs[16][64];

    const int tid = threadIdx.x;
    const int m0 = blockIdx.y * 64;
    const int n0 = blockIdx.x * 64;
    const int tm = tid >> 4;         // 0..15
    const int tn = tid & 15;         // 0..15

    const int aRow = tid >> 2;       // 0..63
    const int aCol = (tid & 3) * 4;  // 0,4,8,12
    const int bRow = tid >> 4;       // 0..15
    const int bCol = (tid & 15) * 4; // 0..60

    float acc[4][4];
#pragma unroll
    for (int r = 0; r < 4; r++)
#pragma unroll
        for (int c = 0; c < 4; c++) acc[r][c] = 0.f;

    for (int k0 = 0; k0 < K; k0 += 16) {
        float4 av = *(const float4*)&A[(long)(m0 + aRow) * K + k0 + aCol];
        As[aCol + 0][aRow] = av.x;
        As[aCol + 1][aRow] = av.y;
        As[aCol + 2][aRow] = av.z;
        As[aCol + 3][aRow] = av.w;
#pragma unroll
        for (int q = 0; q < 4; q++) {
            int n = n0 + bCol + q;
            Bs[bRow][bCol + q] = (n < Nw) ? Bm[(long)(k0 + bRow) * Nw + n] : 0.f;
        }
        __syncthreads();
#pragma unroll
        for (int kk = 0; kk < 16; kk++) {
            float4 a4 = *(const float4*)&As[kk][tm * 4];
            float4 b4 = *(const float4*)&Bs[kk][tn * 4];
            float ar[4] = {a4.x, a4.y, a4.z, a4.w};
            float br[4] = {b4.x, b4.y, b4.z, b4.w};
#pragma unroll
            for (int r = 0; r < 4; r++)
#pragma unroll
                for (int c = 0; c < 4; c++) acc[r][c] += ar[r] * br[c];
        }
        __syncthreads();
    }

#pragma unroll
    for (int r = 0; r < 4; r++) {
        int m = m0 + tm * 4 + r;
#pragma unroll
        for (int c = 0; c < 4; c++) {
            int n = n0 + tn * 4 + c;
            if (n < Nw) {
                float v = acc[r][c];
                if (HAS_BIAS) v += bias[n];
                C[(long)m * Nw + n] = v;
            }
        }
    }
}

// ---------------- point transform + vcat fill -------------------------------
// q_pts world -> g_qpts, k_pts -> g_kpts, v_pts world + v copy -> g_vcat
__global__ void pts_kernel(const float* __restrict__ rot, const float* __restrict__ trans) {
    const int i = blockIdx.x;
    const int t = threadIdx.x; // 384
    __shared__ float R[9], T[3];
    if (t < 9) R[t] = rot[i * 9 + t];
    if (t < 3) T[t] = trans[i * 3 + t];
    __syncthreads();

    if (t < 48) {
        // q point t = h*4+p ; local comps at c*48 + t
        float l0 = g_qpl[i * 144 + 0 * 48 + t];
        float l1 = g_qpl[i * 144 + 1 * 48 + t];
        float l2 = g_qpl[i * 144 + 2 * 48 + t];
#pragma unroll
        for (int ci = 0; ci < 3; ci++)
            g_qpts[i * 144 + 3 * t + ci] =
                R[ci * 3 + 0] * l0 + R[ci * 3 + 1] * l1 + R[ci * 3 + 2] * l2 + T[ci];
    } else if (t < 96) {
        int u = t - 48;          // h*4+p
        int h = u >> 2, p = u & 3;
        int pidx = h * 12 + p;   // within 144-wide kv point set
        float l0 = g_kvpl[i * 432 + 0 * 144 + pidx];
        float l1 = g_kvpl[i * 432 + 1 * 144 + pidx];
        float l2 = g_kvpl[i * 432 + 2 * 144 + pidx];
#pragma unroll
        for (int ci = 0; ci < 3; ci++)
            g_kpts[i * 144 + 3 * u + ci] =
                R[ci * 3 + 0] * l0 + R[ci * 3 + 1] * l1 + R[ci * 3 + 2] * l2 + T[ci];
    } else if (t < 192) {
        int u = t - 96;          // h*8+p
        int h = u >> 3, p = u & 7;
        int pidx = h * 12 + 4 + p;
        float l0 = g_kvpl[i * 432 + 0 * 144 + pidx];
        float l1 = g_kvpl[i * 432 + 1 * 144 + pidx];
        float l2 = g_kvpl[i * 432 + 2 * 144 + pidx];
#pragma unroll
        for (int ci = 0; ci < 3; ci++)
            g_vcat[((long)h * NN + i) * 40 + 16 + p * 3 + ci] =
                R[ci * 3 + 0] * l0 + R[ci * 3 + 1] * l1 + R[ci * 3 + 2] * l2 + T[ci];
    } else {
        int u = t - 192;         // h*16+d
        int h = u >> 4, d = u & 15;
        g_vcat[((long)h * NN + i) * 40 + d] = g_kv[i * 384 + h * 32 + 16 + d];
    }
}

// ---------------- b = sqrt(1/3) * (z @ Wb + bb) -> g_a ----------------------
// grid (8 jtiles of 64, 512 i), block 256: thread -> (j = t&63, hgroup = t>>6 -> 3 heads)
__global__ void bz_kernel(const float* __restrict__ z, const float* __restrict__ Wb,
                          const float* __restrict__ bb) {
    __shared__ __align__(16) float zs[64][132];
    __shared__ __align__(16) float wbs_t[12][128];
    __shared__ float bbs[12];

    const int i = blockIdx.y;
    const int j0 = blockIdx.x * 64;
    const int t = threadIdx.x;

    for (int idx = t; idx < 12 * 128; idx += 256) {
        int h = idx >> 7, c = idx & 127;
        wbs_t[h][c] = Wb[c * 12 + h];
    }
    if (t < 12) bbs[t] = bb[t];
    for (int idx = t; idx < 64 * 128; idx += 256) {
        int r = idx >> 7, c = idx & 127;
        zs[r][c] = z[(((long)i << 9) + j0 + r) * 128 + c];
    }
    __syncthreads();

    const int j = t & 63;
    const int g = t >> 6;  // 0..3, heads g*3 .. g*3+2
    float a0 = 0.f, a1 = 0.f, a2 = 0.f;
#pragma unroll 4
    for (int c4 = 0; c4 < 32; c4++) {
        float4 zv = *(const float4*)&zs[j][c4 * 4];
        float4 w0 = *(const float4*)&wbs_t[g * 3 + 0][c4 * 4];
        float4 w1 = *(const float4*)&wbs_t[g * 3 + 1][c4 * 4];
        float4 w2 = *(const float4*)&wbs_t[g * 3 + 2][c4 * 4];
        a0 += zv.x * w0.x + zv.y * w0.y + zv.z * w0.z + zv.w * w0.w;
        a1 += zv.x * w1.x + zv.y * w1.y + zv.z * w1.z + zv.w * w1.w;
        a2 += zv.x * w2.x + zv.y * w2.y + zv.z * w2.z + zv.w * w2.w;
    }
    const float k13 = 0.57735026918962576f; // sqrt(1/3)
    g_a[(((long)(g * 3 + 0) << 9) + i) * 512 + j0 + j] = k13 * (a0 + bbs[g * 3 + 0]);
    g_a[(((long)(g * 3 + 1) << 9) + i) * 512 + j0 + j] = k13 * (a1 + bbs[g * 3 + 1]);
    g_a[(((long)(g * 3 + 2) << 9) + i) * 512 + j0 + j] = k13 * (a2 + bbs[g * 3 + 2]);
}

// ---------------- logits: a += qk*scale + pt_att + mask ---------------------
// grid (16 jb, 16 ib, 12 h), block 256, each thread 4 outputs
__global__ void logits_kernel(const float* __restrict__ mask, const float* __restrict__ head_w) {
    const int h = blockIdx.z;
    const int i0 = blockIdx.y * 32;
    const int j0 = blockIdx.x * 32;
    __shared__ float qs[32][16], ks[32][16];
    __shared__ float qps[32][12], kps[32][12];
    __shared__ float mi[32], mj[32];
    const int t = threadIdx.x;

    for (int idx = t; idx < 512; idx += 256) {
        int r = idx >> 4, d = idx & 15;
        qs[r][d] = g_q[(i0 + r) * 192 + h * 16 + d];
        ks[r][d] = g_kv[(j0 + r) * 384 + h * 32 + d];
    }
    for (int idx = t; idx < 384; idx += 256) {
        int r = idx / 12, pc = idx % 12;
        qps[r][pc] = g_qpts[(i0 + r) * 144 + h * 12 + pc];
        kps[r][pc] = g_kpts[(j0 + r) * 144 + h * 12 + pc];
    }
    if (t < 32) { mi[t] = mask[i0 + t]; mj[t] = mask[j0 + t]; }
    __syncthreads();

    float x = head_w[h];
    float sp = (x > 20.f) ? x : log1pf(expf(x));
    float hw = sp * 0.13608276348795434f; // sqrt(1/54)
    const float kqk = 0.14433756729740643f; // sqrt(1/48)

    const int ii = t >> 3;
    const int jj0 = (t & 7) << 2;
#pragma unroll
    for (int q = 0; q < 4; q++) {
        int jj = jj0 + q;
        float dot = 0.f;
#pragma unroll
        for (int d = 0; d < 16; d++) dot += qs[ii][d] * ks[jj][d];
        float pt = 0.f;
#pragma unroll
        for (int pc = 0; pc < 12; pc++) {
            float df = qps[ii][pc] - kps[jj][pc];
            pt += df * df;
        }
        float val = dot * kqk - 0.5f * hw * pt + 100000.0f * (mi[ii] * mj[jj] - 1.0f);
        g_a[(((long)h << 9) + i0 + ii) * 512 + j0 + jj] += val;
    }
}

// ---------------- softmax over j ------------------------------------------
__global__ void softmax_kernel() {
    const int i = blockIdx.x, h = blockIdx.y;
    float* row = g_a + (((long)h << 9) + i) * 512;
    const int t = threadIdx.x; // 256
    float v0 = row[t], v1 = row[t + 256];

    float m = fmaxf(v0, v1);
#pragma unroll
    for (int o = 16; o; o >>= 1) m = fmaxf(m, __shfl_xor_sync(0xffffffffu, m, o));
    __shared__ float redm[8], reds[8];
    const int w = t >> 5, lane = t & 31;
    if (lane == 0) redm[w] = m;
    __syncthreads();
    m = redm[0];
#pragma unroll
    for (int q = 1; q < 8; q++) m = fmaxf(m, redm[q]);

    float e0 = expf(v0 - m), e1 = expf(v1 - m);
    float s = e0 + e1;
#pragma unroll
    for (int o = 16; o; o >>= 1) s += __shfl_xor_sync(0xffffffffu, s, o);
    if (lane == 0) reds[w] = s;
    __syncthreads();
    s = reds[0];
#pragma unroll
    for (int q = 1; q < 8; q++) s += reds[q];

    float inv = 1.f / s;
    row[t] = e0 * inv;
    row[t + 256] = e1 * inv;
}

// ---------------- o_pair[i,h,c] = sum_j a[h,i,j] * z[i,j,c] -> cat ----------
__global__ void opair_kernel(const float* __restrict__ z) {
    const int i = blockIdx.x;
    __shared__ float sa[12][512];
    __shared__ __align__(16) float zs[32][128];
    const int t = threadIdx.x; // 256

    for (int idx = t; idx < 12 * 512; idx += 256) {
        int h = idx >> 9, j = idx & 511;
        sa[h][j] = g_a[(((long)h << 9) + i) * 512 + j];
    }

    const int c = t & 127;
    const int hh = t >> 7; // 0/1 -> heads hh*6 .. +5
    float acc[6] = {0.f, 0.f, 0.f, 0.f, 0.f, 0.f};

    for (int j0 = 0; j0 < 512; j0 += 32) {
        __syncthreads();
        for (int idx = t; idx < 32 * 128; idx += 256) {
            int r = idx >> 7, cc = idx & 127;
            zs[r][cc] = z[(((long)i << 9) + j0 + r) * 128 + cc];
        }
        __syncthreads();
#pragma unroll 4
        for (int r = 0; r < 32; r++) {
            float zv = zs[r][c];
#pragma unroll
            for (int q = 0; q < 6; q++) acc[q] += sa[hh * 6 + q][j0 + r] * zv;
        }
    }
#pragma unroll
    for (int q = 0; q < 6; q++)
        g_cat[(long)i * 2112 + 576 + (hh * 6 + q) * 128 + c] = acc[q];
}

// ---------------- assemble: o copy + inverse-frame o_pt + norms -------------
__global__ void assemble_kernel(const float* __restrict__ rot, const float* __restrict__ trans) {
    const int i = blockIdx.x;
    const int t = threadIdx.x; // 192
    __shared__ float R[9], T[3];
    if (t < 9) R[t] = rot[i * 9 + t];
    if (t < 3) T[t] = trans[i * 3 + t];
    __syncthreads();

    { // o copy: t = h*16+d
        int h = t >> 4, d = t & 15;
        g_cat[(long)i * 2112 + t] = g_o1[((long)h * NN + i) * 40 + d];
    }
    if (t < 96) { // point t = h*8+p
        int h = t >> 3, p = t & 7;
        const float* src = &g_o1[((long)h * NN + i) * 40 + 16 + p * 3];
        float w0 = src[0] - T[0];
        float w1 = src[1] - T[1];
        float w2 = src[2] - T[2];
        float l0 = R[0] * w0 + R[3] * w1 + R[6] * w2;
        float l1 = R[1] * w0 + R[4] * w1 + R[7] * w2;
        float l2 = R[2] * w0 + R[5] * w1 + R[8] * w2;
        g_cat[(long)i * 2112 + 192 + t] = l0;
        g_cat[(long)i * 2112 + 288 + t] = l1;
        g_cat[(long)i * 2112 + 384 + t] = l2;
        g_cat[(long)i * 2112 + 480 + t] = sqrtf(l0 * l0 + l1 * l1 + l2 * l2 + 1e-8f);
    }
}

// ---------------- launch ----------------------------------------------------
extern "C" void kernel_launch(void* const* d_in, const int* in_sizes, int n_in,
                              void* d_out, int out_size) {
    const float* s     = (const float*)d_in[0];
    const float* z     = (const float*)d_in[1];
    const float* rot   = (const float*)d_in[2];
    const float* trans = (const float*)d_in[3];
    const float* mask  = (const float*)d_in[4];
    const float* Wq    = (const float*)d_in[5];
    const float* bq    = (const float*)d_in[6];
    const float* Wkv   = (const float*)d_in[7];
    const float* bkv   = (const float*)d_in[8];
    const float* Wqp   = (const float*)d_in[9];
    const float* bqp   = (const float*)d_in[10];
    const float* Wkvp  = (const float*)d_in[11];
    const float* bkvp  = (const float*)d_in[12];
    const float* Wb    = (const float*)d_in[13];
    const float* bb    = (const float*)d_in[14];
    const float* head_w= (const float*)d_in[15];
    const float* Wout  = (const float*)d_in[16];
    const float* bout  = (const float*)d_in[17];
    float* out = (float*)d_out;

    float *pq, *pkv, *pqpl, *pkvpl, *pa, *pvcat, *po1, *pcat;
    cudaGetSymbolAddress((void**)&pq, g_q);
    cudaGetSymbolAddress((void**)&pkv, g_kv);
    cudaGetSymbolAddress((void**)&pqpl, g_qpl);
    cudaGetSymbolAddress((void**)&pkvpl, g_kvpl);
    cudaGetSymbolAddress((void**)&pa, g_a);
    cudaGetSymbolAddress((void**)&pvcat, g_vcat);
    cudaGetSymbolAddress((void**)&po1, g_o1);
    cudaGetSymbolAddress((void**)&pcat, g_cat);

    // projections from s
    gemm_kernel<true><<<dim3(3, 8, 1), 256>>>(s, Wq, bq, pq, 512, 1024, 192, 0, 0, 0);
    gemm_kernel<true><<<dim3(6, 8, 1), 256>>>(s, Wkv, bkv, pkv, 512, 1024, 384, 0, 0, 0);
    gemm_kernel<true><<<dim3(3, 8, 1), 256>>>(s, Wqp, bqp, pqpl, 512, 1024, 144, 0, 0, 0);
    gemm_kernel<true><<<dim3(7, 8, 1), 256>>>(s, Wkvp, bkvp, pkvpl, 512, 1024, 432, 0, 0, 0);

    pts_kernel<<<512, 384>>>(rot, trans);
    bz_kernel<<<dim3(8, 512), 256>>>(z, Wb, bb);
    logits_kernel<<<dim3(16, 16, 12), 256>>>(mask, head_w);
    softmax_kernel<<<dim3(512, 12), 256>>>();

    // per-head: [a(512x512)] @ [v|v_pts](512x40) -> o1
    gemm_kernel<false><<<dim3(1, 8, 12), 256>>>(pa, pvcat, nullptr, po1, 512, 512, 40,
                                                (long)512 * 512, (long)512 * 40, (long)512 * 40);
    opair_kernel<<<512, 256>>>(z);
    assemble_kernel<<<512, 192>>>(rot, trans);

    // final: cat(512x2112) @ Wout(2112x1024) + bout -> out
    gemm_kernel<true><<<dim3(16, 8, 1), 256>>>(pcat, Wout, bout, out, 512, 2112, 1024, 0, 0, 0);
}

// round 6
// speedup vs baseline: 1.4757x; 1.4757x over previous
#include <cuda_runtime.h>
#include <math.h>

#define NN 512
#define CS 1024
#define CZd 128
#define Hh 12
#define HDd 16
#define PQp 4
#define PVp 8
#define NPROJ 1152   // 192 q | 384 kv | 144 qp | 432 kvp

// ---------------- scratch (device globals; no allocation allowed) ----------
__device__ __align__(16) float g_W[CS * NPROJ];             // packed proj weights
__device__ __align__(16) float g_bias[NPROJ];               // packed proj bias
__device__ __align__(16) float g_proj[NN * NPROJ];          // fused projection out
__device__ __align__(16) float g_qpts[NN * Hh * PQp * 3];   // [i][h*12 + p*3 + c] world
__device__ __align__(16) float g_kpts[NN * Hh * PQp * 3];   // [i][h*12 + p*3 + c] world
__device__ __align__(16) float g_vcat[Hh * NN * 40];        // [h][j][0:16 v | 16:40 vpts world]
__device__ __align__(16) float g_a[Hh * NN * NN];           // logits / attn
__device__ __align__(16) float g_o1[Hh * NN * 40];          // a @ vcat
__device__ __align__(16) float g_cat[NN * 2112];            // concat buffer

// ---------------- pack proj weights/bias into one matrix --------------------
__global__ void pack_kernel(const float* __restrict__ Wq, const float* __restrict__ Wkv,
                            const float* __restrict__ Wqp, const float* __restrict__ Wkvp,
                            const float* __restrict__ bq, const float* __restrict__ bkv,
                            const float* __restrict__ bqp, const float* __restrict__ bkvp) {
    int idx = blockIdx.x * 256 + threadIdx.x;
    if (idx < CS * NPROJ) {
        int k = idx / NPROJ, c = idx % NPROJ;
        float v;
        if (c < 192) v = Wq[k * 192 + c];
        else if (c < 576) v = Wkv[k * 384 + (c - 192)];
        else if (c < 720) v = Wqp[k * 144 + (c - 576)];
        else v = Wkvp[k * 432 + (c - 720)];
        g_W[idx] = v;
    }
    if (idx < NPROJ) {
        int c = idx;
        float v;
        if (c < 192) v = bq[c];
        else if (c < 576) v = bkv[c - 192];
        else if (c < 720) v = bqp[c - 576];
        else v = bkvp[c - 720];
        g_bias[c] = v;
    }
}

// ---------------- double-buffered SGEMM: C = A(MxK) @ B(KxNw) (+bias) -------
// BM=BN=64, BK=16, 256 threads, 4x4 per thread.
// Requires: M % 64 == 0, K % 16 == 0, Nw % 4 == 0.
template <bool HAS_BIAS>
__global__ __launch_bounds__(256)
void gemm64(const float* __restrict__ A, const float* __restrict__ Bm,
            const float* __restrict__ bias, float* __restrict__ C,
            int M, int K, int Nw, long sA, long sB, long sC) {
    A += blockIdx.z * sA;
    Bm += blockIdx.z * sB;
    C += blockIdx.z * sC;

    __shared__ __align__(16) float As[2][16][68];  // transposed, padded (no conflicts)
    __shared__ __align__(16) float Bs[2][16][64];

    const int tid = threadIdx.x;
    const int m0 = blockIdx.y * 64;
    const int n0 = blockIdx.x * 64;

    const int aRow = tid >> 2;          // 0..63
    const int aCol = (tid & 3) * 4;     // 0,4,8,12
    const int bRow = tid >> 4;          // 0..15
    const int bCol = (tid & 15) * 4;    // 0..60
    const int tm = tid >> 4;            // 0..15
    const int tn = tid & 15;            // 0..15

    const float* Ag = A + (long)(m0 + aRow) * K + aCol;
    const float* Bg = Bm + (long)bRow * Nw + n0 + bCol;
    const bool bPred = (n0 + bCol + 3) < Nw;  // Nw % 4 == 0 -> float4-granular

    // prologue: tile 0
    float4 ra = *(const float4*)Ag;
    float4 rb = bPred ? *(const float4*)Bg : make_float4(0.f, 0.f, 0.f, 0.f);
    As[0][aCol + 0][aRow] = ra.x;
    As[0][aCol + 1][aRow] = ra.y;
    As[0][aCol + 2][aRow] = ra.z;
    As[0][aCol + 3][aRow] = ra.w;
    *(float4*)&Bs[0][bRow][bCol] = rb;
    __syncthreads();

    float acc[4][4];
#pragma unroll
    for (int r = 0; r < 4; r++)
#pragma unroll
        for (int c = 0; c < 4; c++) acc[r][c] = 0.f;

    const int T = K >> 4;
    for (int t = 0; t < T; t++) {
        const int cur = t & 1;
        if (t + 1 < T) {
            ra = *(const float4*)(Ag + (t + 1) * 16);
            rb = bPred ? *(const float4*)(Bg + (long)(t + 1) * 16 * Nw)
                       : make_float4(0.f, 0.f, 0.f, 0.f);
        }
#pragma unroll
        for (int kk = 0; kk < 16; kk++) {
            float4 a4 = *(const float4*)&As[cur][kk][tm * 4];
            float4 b4 = *(const float4*)&Bs[cur][kk][tn * 4];
            float ar[4] = {a4.x, a4.y, a4.z, a4.w};
            float br[4] = {b4.x, b4.y, b4.z, b4.w};
#pragma unroll
            for (int r = 0; r < 4; r++)
#pragma unroll
                for (int c = 0; c < 4; c++) acc[r][c] += ar[r] * br[c];
        }
        if (t + 1 < T) {
            const int nxt = cur ^ 1;
            As[nxt][aCol + 0][aRow] = ra.x;
            As[nxt][aCol + 1][aRow] = ra.y;
            As[nxt][aCol + 2][aRow] = ra.z;
            As[nxt][aCol + 3][aRow] = ra.w;
            *(float4*)&Bs[nxt][bRow][bCol] = rb;
            __syncthreads();
        }
    }

#pragma unroll
    for (int r = 0; r < 4; r++) {
        const int m = m0 + tm * 4 + r;
#pragma unroll
        for (int c = 0; c < 4; c++) {
            const int n = n0 + tn * 4 + c;
            if (n < Nw) {
                float v = acc[r][c];
                if (HAS_BIAS) v += bias[n];
                C[(long)m * Nw + n] = v;
            }
        }
    }
}

// ---------------- point transform + vcat fill -------------------------------
__global__ void pts_kernel(const float* __restrict__ rot, const float* __restrict__ trans) {
    const int i = blockIdx.x;
    const int t = threadIdx.x; // 384
    __shared__ float R[9], T[3];
    if (t < 9) R[t] = rot[i * 9 + t];
    if (t < 3) T[t] = trans[i * 3 + t];
    __syncthreads();

    const float* P = g_proj + (long)i * NPROJ;

    if (t < 48) {
        // q point t = h*4+p ; local comps at 576 + c*48 + t
        float l0 = P[576 + 0 * 48 + t];
        float l1 = P[576 + 1 * 48 + t];
        float l2 = P[576 + 2 * 48 + t];
#pragma unroll
        for (int ci = 0; ci < 3; ci++)
            g_qpts[i * 144 + 3 * t + ci] =
                R[ci * 3 + 0] * l0 + R[ci * 3 + 1] * l1 + R[ci * 3 + 2] * l2 + T[ci];
    } else if (t < 96) {
        int u = t - 48;          // h*4+p
        int h = u >> 2, p = u & 3;
        int pidx = h * 12 + p;
        float l0 = P[720 + 0 * 144 + pidx];
        float l1 = P[720 + 1 * 144 + pidx];
        float l2 = P[720 + 2 * 144 + pidx];
#pragma unroll
        for (int ci = 0; ci < 3; ci++)
            g_kpts[i * 144 + 3 * u + ci] =
                R[ci * 3 + 0] * l0 + R[ci * 3 + 1] * l1 + R[ci * 3 + 2] * l2 + T[ci];
    } else if (t < 192) {
        int u = t - 96;          // h*8+p
        int h = u >> 3, p = u & 7;
        int pidx = h * 12 + 4 + p;
        float l0 = P[720 + 0 * 144 + pidx];
        float l1 = P[720 + 1 * 144 + pidx];
        float l2 = P[720 + 2 * 144 + pidx];
#pragma unroll
        for (int ci = 0; ci < 3; ci++)
            g_vcat[((long)h * NN + i) * 40 + 16 + p * 3 + ci] =
                R[ci * 3 + 0] * l0 + R[ci * 3 + 1] * l1 + R[ci * 3 + 2] * l2 + T[ci];
    } else {
        int u = t - 192;         // h*16+d
        int h = u >> 4, d = u & 15;
        g_vcat[((long)h * NN + i) * 40 + d] = P[192 + h * 32 + 16 + d];
    }
}

// ---------------- b = sqrt(1/3) * (z @ Wb + bb) -> g_a ----------------------
__global__ void bz_kernel(const float* __restrict__ z, const float* __restrict__ Wb,
                          const float* __restrict__ bb) {
    __shared__ __align__(16) float zs[64][132];
    __shared__ __align__(16) float wbs_t[12][128];
    __shared__ float bbs[12];

    const int i = blockIdx.y;
    const int j0 = blockIdx.x * 64;
    const int t = threadIdx.x;

    for (int idx = t; idx < 12 * 128; idx += 256) {
        int h = idx >> 7, c = idx & 127;
        wbs_t[h][c] = Wb[c * 12 + h];
    }
    if (t < 12) bbs[t] = bb[t];
    for (int idx = t; idx < 64 * 128; idx += 256) {
        int r = idx >> 7, c = idx & 127;
        zs[r][c] = z[(((long)i << 9) + j0 + r) * 128 + c];
    }
    __syncthreads();

    const int j = t & 63;
    const int g = t >> 6;  // 0..3, heads g*3 .. g*3+2
    float a0 = 0.f, a1 = 0.f, a2 = 0.f;
#pragma unroll 4
    for (int c4 = 0; c4 < 32; c4++) {
        float4 zv = *(const float4*)&zs[j][c4 * 4];
        float4 w0 = *(const float4*)&wbs_t[g * 3 + 0][c4 * 4];
        float4 w1 = *(const float4*)&wbs_t[g * 3 + 1][c4 * 4];
        float4 w2 = *(const float4*)&wbs_t[g * 3 + 2][c4 * 4];
        a0 += zv.x * w0.x + zv.y * w0.y + zv.z * w0.z + zv.w * w0.w;
        a1 += zv.x * w1.x + zv.y * w1.y + zv.z * w1.z + zv.w * w1.w;
        a2 += zv.x * w2.x + zv.y * w2.y + zv.z * w2.z + zv.w * w2.w;
    }
    const float k13 = 0.57735026918962576f; // sqrt(1/3)
    g_a[(((long)(g * 3 + 0) << 9) + i) * 512 + j0 + j] = k13 * (a0 + bbs[g * 3 + 0]);
    g_a[(((long)(g * 3 + 1) << 9) + i) * 512 + j0 + j] = k13 * (a1 + bbs[g * 3 + 1]);
    g_a[(((long)(g * 3 + 2) << 9) + i) * 512 + j0 + j] = k13 * (a2 + bbs[g * 3 + 2]);
}

// ---------------- logits: a += qk*scale + pt_att + mask ---------------------
__global__ void logits_kernel(const float* __restrict__ mask, const float* __restrict__ head_w) {
    const int h = blockIdx.z;
    const int i0 = blockIdx.y * 32;
    const int j0 = blockIdx.x * 32;
    __shared__ float qs[32][16], ks[32][16];
    __shared__ float qps[32][12], kps[32][12];
    __shared__ float mi[32], mj[32];
    const int t = threadIdx.x;

    for (int idx = t; idx < 512; idx += 256) {
        int r = idx >> 4, d = idx & 15;
        qs[r][d] = g_proj[(long)(i0 + r) * NPROJ + h * 16 + d];
        ks[r][d] = g_proj[(long)(j0 + r) * NPROJ + 192 + h * 32 + d];
    }
    for (int idx = t; idx < 384; idx += 256) {
        int r = idx / 12, pc = idx % 12;
        qps[r][pc] = g_qpts[(i0 + r) * 144 + h * 12 + pc];
        kps[r][pc] = g_kpts[(j0 + r) * 144 + h * 12 + pc];
    }
    if (t < 32) { mi[t] = mask[i0 + t]; mj[t] = mask[j0 + t]; }
    __syncthreads();

    float x = head_w[h];
    float sp = (x > 20.f) ? x : log1pf(expf(x));
    float hw = sp * 0.13608276348795434f; // sqrt(1/54)
    const float kqk = 0.14433756729740643f; // sqrt(1/48)

    const int ii = t >> 3;
    const int jj0 = (t & 7) << 2;
#pragma unroll
    for (int q = 0; q < 4; q++) {
        int jj = jj0 + q;
        float dot = 0.f;
#pragma unroll
        for (int d = 0; d < 16; d++) dot += qs[ii][d] * ks[jj][d];
        float pt = 0.f;
#pragma unroll
        for (int pc = 0; pc < 12; pc++) {
            float df = qps[ii][pc] - kps[jj][pc];
            pt += df * df;
        }
        float val = dot * kqk - 0.5f * hw * pt + 100000.0f * (mi[ii] * mj[jj] - 1.0f);
        g_a[(((long)h << 9) + i0 + ii) * 512 + j0 + jj] += val;
    }
}

// ---------------- softmax over j ------------------------------------------
__global__ void softmax_kernel() {
    const int i = blockIdx.x, h = blockIdx.y;
    float* row = g_a + (((long)h << 9) + i) * 512;
    const int t = threadIdx.x; // 256
    float v0 = row[t], v1 = row[t + 256];

    float m = fmaxf(v0, v1);
#pragma unroll
    for (int o = 16; o; o >>= 1) m = fmaxf(m, __shfl_xor_sync(0xffffffffu, m, o));
    __shared__ float redm[8], reds[8];
    const int w = t >> 5, lane = t & 31;
    if (lane == 0) redm[w] = m;
    __syncthreads();
    m = redm[0];
#pragma unroll
    for (int q = 1; q < 8; q++) m = fmaxf(m, redm[q]);

    float e0 = expf(v0 - m), e1 = expf(v1 - m);
    float s = e0 + e1;
#pragma unroll
    for (int o = 16; o; o >>= 1) s += __shfl_xor_sync(0xffffffffu, s, o);
    if (lane == 0) reds[w] = s;
    __syncthreads();
    s = reds[0];
#pragma unroll
    for (int q = 1; q < 8; q++) s += reds[q];

    float inv = 1.f / s;
    row[t] = e0 * inv;
    row[t + 256] = e1 * inv;
}

// ---------------- o_pair[i,h,c] = sum_j a[h,i,j] * z[i,j,c] -> cat ----------
__global__ void opair_kernel(const float* __restrict__ z) {
    const int i = blockIdx.x;
    __shared__ float sa[12][512];
    __shared__ __align__(16) float zs[32][128];
    const int t = threadIdx.x; // 256

    for (int idx = t; idx < 12 * 512; idx += 256) {
        int h = idx >> 9, j = idx & 511;
        sa[h][j] = g_a[(((long)h << 9) + i) * 512 + j];
    }

    const int c = t & 127;
    const int hh = t >> 7; // 0/1 -> heads hh*6 .. +5
    float acc[6] = {0.f, 0.f, 0.f, 0.f, 0.f, 0.f};

    for (int j0 = 0; j0 < 512; j0 += 32) {
        __syncthreads();
        for (int idx = t; idx < 32 * 128; idx += 256) {
            int r = idx >> 7, cc = idx & 127;
            zs[r][cc] = z[(((long)i << 9) + j0 + r) * 128 + cc];
        }
        __syncthreads();
#pragma unroll 4
        for (int r = 0; r < 32; r++) {
            float zv = zs[r][c];
#pragma unroll
            for (int q = 0; q < 6; q++) acc[q] += sa[hh * 6 + q][j0 + r] * zv;
        }
    }
#pragma unroll
    for (int q = 0; q < 6; q++)
        g_cat[(long)i * 2112 + 576 + (hh * 6 + q) * 128 + c] = acc[q];
}

// ---------------- assemble: o copy + inverse-frame o_pt + norms -------------
__global__ void assemble_kernel(const float* __restrict__ rot, const float* __restrict__ trans) {
    const int i = blockIdx.x;
    const int t = threadIdx.x; // 192
    __shared__ float R[9], T[3];
    if (t < 9) R[t] = rot[i * 9 + t];
    if (t < 3) T[t] = trans[i * 3 + t];
    __syncthreads();

    { // o copy: t = h*16+d
        int h = t >> 4, d = t & 15;
        g_cat[(long)i * 2112 + t] = g_o1[((long)h * NN + i) * 40 + d];
    }
    if (t < 96) { // point t = h*8+p
        int h = t >> 3, p = t & 7;
        const float* src = &g_o1[((long)h * NN + i) * 40 + 16 + p * 3];
        float w0 = src[0] - T[0];
        float w1 = src[1] - T[1];
        float w2 = src[2] - T[2];
        float l0 = R[0] * w0 + R[3] * w1 + R[6] * w2;
        float l1 = R[1] * w0 + R[4] * w1 + R[7] * w2;
        float l2 = R[2] * w0 + R[5] * w1 + R[8] * w2;
        g_cat[(long)i * 2112 + 192 + t] = l0;
        g_cat[(long)i * 2112 + 288 + t] = l1;
        g_cat[(long)i * 2112 + 384 + t] = l2;
        g_cat[(long)i * 2112 + 480 + t] = sqrtf(l0 * l0 + l1 * l1 + l2 * l2 + 1e-8f);
    }
}

// ---------------- launch ----------------------------------------------------
extern "C" void kernel_launch(void* const* d_in, const int* in_sizes, int n_in,
                              void* d_out, int out_size) {
    const float* s     = (const float*)d_in[0];
    const float* z     = (const float*)d_in[1];
    const float* rot   = (const float*)d_in[2];
    const float* trans = (const float*)d_in[3];
    const float* mask  = (const float*)d_in[4];
    const float* Wq    = (const float*)d_in[5];
    const float* bq    = (const float*)d_in[6];
    const float* Wkv   = (const float*)d_in[7];
    const float* bkv   = (const float*)d_in[8];
    const float* Wqp   = (const float*)d_in[9];
    const float* bqp   = (const float*)d_in[10];
    const float* Wkvp  = (const float*)d_in[11];
    const float* bkvp  = (const float*)d_in[12];
    const float* Wb    = (const float*)d_in[13];
    const float* bb    = (const float*)d_in[14];
    const float* head_w= (const float*)d_in[15];
    const float* Wout  = (const float*)d_in[16];
    const float* bout  = (const float*)d_in[17];
    float* out = (float*)d_out;

    float *pW, *pBias, *pProj, *pA, *pVcat, *pO1, *pCat;
    cudaGetSymbolAddress((void**)&pW, g_W);
    cudaGetSymbolAddress((void**)&pBias, g_bias);
    cudaGetSymbolAddress((void**)&pProj, g_proj);
    cudaGetSymbolAddress((void**)&pA, g_a);
    cudaGetSymbolAddress((void**)&pVcat, g_vcat);
    cudaGetSymbolAddress((void**)&pO1, g_o1);
    cudaGetSymbolAddress((void**)&pCat, g_cat);

    // pack fused projection weights (1024x1152) + bias
    pack_kernel<<<(CS * NPROJ + 255) / 256, 256>>>(Wq, Wkv, Wqp, Wkvp, bq, bkv, bqp, bkvp);

    // fused projection: s(512x1024) @ W(1024x1152) + bias -> g_proj
    gemm64<true><<<dim3(NPROJ / 64, 8, 1), 256>>>(s, pW, pBias, pProj, 512, 1024, NPROJ, 0, 0, 0);

    pts_kernel<<<512, 384>>>(rot, trans);
    bz_kernel<<<dim3(8, 512), 256>>>(z, Wb, bb);
    logits_kernel<<<dim3(16, 16, 12), 256>>>(mask, head_w);
    softmax_kernel<<<dim3(512, 12), 256>>>();

    // per-head: [a(512x512)] @ [v|v_pts](512x40) -> o1
    gemm64<false><<<dim3(1, 8, 12), 256>>>(pA, pVcat, nullptr, pO1, 512, 512, 40,
                                           (long)512 * 512, (long)512 * 40, (long)512 * 40);
    opair_kernel<<<512, 256>>>(z);
    assemble_kernel<<<512, 192>>>(rot, trans);

    // final: cat(512x2112) @ Wout(2112x1024) + bout -> out
    gemm64<true><<<dim3(16, 8, 1), 256>>>(pCat, Wout, bout, out, 512, 2112, 1024, 0, 0, 0);
}

// round 8
// speedup vs baseline: 1.6636x; 1.1273x over previous
#include <cuda_runtime.h>
#include <math.h>

#define NN 512
#define CS 1024
#define CZd 128
#define Hh 12
#define HDd 16
#define PQp 4
#define PVp 8
#define NPROJ 1152   // 192 q | 384 kv | 144 qp | 432 kvp

// ---------------- scratch (device globals; no allocation allowed) ----------
__device__ __align__(16) float g_W[CS * NPROJ];             // packed proj weights
__device__ __align__(16) float g_bias[NPROJ];               // packed proj bias
__device__ __align__(16) float g_proj[NN * NPROJ];          // fused projection out
__device__ __align__(16) float g_qpts[NN * Hh * PQp * 3];   // [i][h*12 + p*3 + c] world
__device__ __align__(16) float g_kpts[NN * Hh * PQp * 3];   // [i][h*12 + p*3 + c] world
__device__ __align__(16) float g_vcat[Hh * NN * 40];        // [h][j][0:16 v | 16:40 vpts world]
__device__ __align__(16) float g_a[Hh * NN * NN];           // logits / attn
__device__ __align__(16) float g_o1[Hh * NN * 40];          // a @ vcat
__device__ __align__(16) float g_cat[NN * 2112];            // concat buffer

// ---------------- pack proj weights/bias into one matrix --------------------
__global__ void pack_kernel(const float* __restrict__ Wq, const float* __restrict__ Wkv,
                            const float* __restrict__ Wqp, const float* __restrict__ Wkvp,
                            const float* __restrict__ bq, const float* __restrict__ bkv,
                            const float* __restrict__ bqp, const float* __restrict__ bkvp) {
    int idx = blockIdx.x * 256 + threadIdx.x;
    if (idx < CS * NPROJ) {
        int k = idx / NPROJ, c = idx % NPROJ;
        float v;
        if (c < 192) v = Wq[k * 192 + c];
        else if (c < 576) v = Wkv[k * 384 + (c - 192)];
        else if (c < 720) v = Wqp[k * 144 + (c - 576)];
        else v = Wkvp[k * 432 + (c - 720)];
        g_W[idx] = v;
    }
    if (idx < NPROJ) {
        int c = idx;
        float v;
        if (c < 192) v = bq[c];
        else if (c < 576) v = bkv[c - 192];
        else if (c < 720) v = bqp[c - 576];
        else v = bkvp[c - 720];
        g_bias[c] = v;
    }
}

// ---------------- double-buffered SGEMM: C = A(MxK) @ B(KxNw) (+bias) -------
// BM=BN=64, BK=16, 256 threads, 4x4 per thread.
// Requires: M % 64 == 0, K % 16 == 0, Nw % 4 == 0.
template <bool HAS_BIAS>
__global__ __launch_bounds__(256)
void gemm64(const float* __restrict__ A, const float* __restrict__ Bm,
            const float* __restrict__ bias, float* __restrict__ C,
            int M, int K, int Nw, long sA, long sB, long sC) {
    A += blockIdx.z * sA;
    Bm += blockIdx.z * sB;
    C += blockIdx.z * sC;

    __shared__ __align__(16) float As[2][16][68];
    __shared__ __align__(16) float Bs[2][16][64];

    const int tid = threadIdx.x;
    const int m0 = blockIdx.y * 64;
    const int n0 = blockIdx.x * 64;

    const int aRow = tid >> 2;
    const int aCol = (tid & 3) * 4;
    const int bRow = tid >> 4;
    const int bCol = (tid & 15) * 4;
    const int tm = tid >> 4;
    const int tn = tid & 15;

    const float* Ag = A + (long)(m0 + aRow) * K + aCol;
    const float* Bg = Bm + (long)bRow * Nw + n0 + bCol;
    const bool bPred = (n0 + bCol + 3) < Nw;

    float4 ra = *(const float4*)Ag;
    float4 rb = bPred ? *(const float4*)Bg : make_float4(0.f, 0.f, 0.f, 0.f);
    As[0][aCol + 0][aRow] = ra.x;
    As[0][aCol + 1][aRow] = ra.y;
    As[0][aCol + 2][aRow] = ra.z;
    As[0][aCol + 3][aRow] = ra.w;
    *(float4*)&Bs[0][bRow][bCol] = rb;
    __syncthreads();

    float acc[4][4];
#pragma unroll
    for (int r = 0; r < 4; r++)
#pragma unroll
        for (int c = 0; c < 4; c++) acc[r][c] = 0.f;

    const int T = K >> 4;
    for (int t = 0; t < T; t++) {
        const int cur = t & 1;
        if (t + 1 < T) {
            ra = *(const float4*)(Ag + (t + 1) * 16);
            rb = bPred ? *(const float4*)(Bg + (long)(t + 1) * 16 * Nw)
                       : make_float4(0.f, 0.f, 0.f, 0.f);
        }
#pragma unroll
        for (int kk = 0; kk < 16; kk++) {
            float4 a4 = *(const float4*)&As[cur][kk][tm * 4];
            float4 b4 = *(const float4*)&Bs[cur][kk][tn * 4];
            float ar[4] = {a4.x, a4.y, a4.z, a4.w};
            float br[4] = {b4.x, b4.y, b4.z, b4.w};
#pragma unroll
            for (int r = 0; r < 4; r++)
#pragma unroll
                for (int c = 0; c < 4; c++) acc[r][c] += ar[r] * br[c];
        }
        if (t + 1 < T) {
            const int nxt = cur ^ 1;
            As[nxt][aCol + 0][aRow] = ra.x;
            As[nxt][aCol + 1][aRow] = ra.y;
            As[nxt][aCol + 2][aRow] = ra.z;
            As[nxt][aCol + 3][aRow] = ra.w;
            *(float4*)&Bs[nxt][bRow][bCol] = rb;
            __syncthreads();
        }
    }

#pragma unroll
    for (int r = 0; r < 4; r++) {
        const int m = m0 + tm * 4 + r;
#pragma unroll
        for (int c = 0; c < 4; c++) {
            const int n = n0 + tn * 4 + c;
            if (n < Nw) {
                float v = acc[r][c];
                if (HAS_BIAS) v += bias[n];
                C[(long)m * Nw + n] = v;
            }
        }
    }
}

// ---------------- point transform + vcat fill -------------------------------
__global__ void pts_kernel(const float* __restrict__ rot, const float* __restrict__ trans) {
    const int i = blockIdx.x;
    const int t = threadIdx.x; // 384
    __shared__ float R[9], T[3];
    if (t < 9) R[t] = rot[i * 9 + t];
    if (t < 3) T[t] = trans[i * 3 + t];
    __syncthreads();

    const float* P = g_proj + (long)i * NPROJ;

    if (t < 48) {
        float l0 = P[576 + 0 * 48 + t];
        float l1 = P[576 + 1 * 48 + t];
        float l2 = P[576 + 2 * 48 + t];
#pragma unroll
        for (int ci = 0; ci < 3; ci++)
            g_qpts[i * 144 + 3 * t + ci] =
                R[ci * 3 + 0] * l0 + R[ci * 3 + 1] * l1 + R[ci * 3 + 2] * l2 + T[ci];
    } else if (t < 96) {
        int u = t - 48;
        int h = u >> 2, p = u & 3;
        int pidx = h * 12 + p;
        float l0 = P[720 + 0 * 144 + pidx];
        float l1 = P[720 + 1 * 144 + pidx];
        float l2 = P[720 + 2 * 144 + pidx];
#pragma unroll
        for (int ci = 0; ci < 3; ci++)
            g_kpts[i * 144 + 3 * u + ci] =
                R[ci * 3 + 0] * l0 + R[ci * 3 + 1] * l1 + R[ci * 3 + 2] * l2 + T[ci];
    } else if (t < 192) {
        int u = t - 96;
        int h = u >> 3, p = u & 7;
        int pidx = h * 12 + 4 + p;
        float l0 = P[720 + 0 * 144 + pidx];
        float l1 = P[720 + 1 * 144 + pidx];
        float l2 = P[720 + 2 * 144 + pidx];
#pragma unroll
        for (int ci = 0; ci < 3; ci++)
            g_vcat[((long)h * NN + i) * 40 + 16 + p * 3 + ci] =
                R[ci * 3 + 0] * l0 + R[ci * 3 + 1] * l1 + R[ci * 3 + 2] * l2 + T[ci];
    } else {
        int u = t - 192;
        int h = u >> 4, d = u & 15;
        g_vcat[((long)h * NN + i) * 40 + d] = P[192 + h * 32 + 16 + d];
    }
}

// ---------------- b = sqrt(1/3) * (z @ Wb + bb) -> g_a ----------------------
// v2: thread-per-j, ALL 12 heads per thread. z smem read once/thread (scalar,
// conflict-free via pad 33); Wb as broadcast float4. FMA-bound.
// grid (2 jtiles of 256, 512 i), block 256.
__global__ __launch_bounds__(256)
void bz_kernel(const float* __restrict__ z, const float* __restrict__ Wb,
               const float* __restrict__ bb) {
    __shared__ float4 ws4[Hh][32];     // Wb^T as float4 over c
    __shared__ float bbs[Hh];
    __shared__ float zs[256][33];      // 32 c per pass, pad 33

    const int i = blockIdx.y;
    const int j0 = blockIdx.x * 256;
    const int t = threadIdx.x;

    for (int idx = t; idx < Hh * 32; idx += 256) {
        int h = idx >> 5, c4 = idx & 31;
        ws4[h][c4] = make_float4(Wb[(c4 * 4 + 0) * Hh + h], Wb[(c4 * 4 + 1) * Hh + h],
                                 Wb[(c4 * 4 + 2) * Hh + h], Wb[(c4 * 4 + 3) * Hh + h]);
    }
    if (t < Hh) bbs[t] = bb[t];

    float acc[Hh];
#pragma unroll
    for (int h = 0; h < Hh; h++) acc[h] = 0.f;

    const int j = t;
    for (int c0 = 0; c0 < 128; c0 += 32) {
        __syncthreads();
        // load 256 x 32 z tile (float4, coalesced)
        for (int idx = t; idx < 256 * 8; idx += 256) {
            int r = idx >> 3, c4 = idx & 7;
            float4 v = *(const float4*)&z[(((long)i << 9) + j0 + r) * 128 + c0 + c4 * 4];
            zs[r][c4 * 4 + 0] = v.x;
            zs[r][c4 * 4 + 1] = v.y;
            zs[r][c4 * 4 + 2] = v.z;
            zs[r][c4 * 4 + 3] = v.w;
        }
        __syncthreads();

        const int wbase = c0 >> 2;
#pragma unroll
        for (int c4 = 0; c4 < 8; c4++) {
            float z0 = zs[j][c4 * 4 + 0];
            float z1 = zs[j][c4 * 4 + 1];
            float z2 = zs[j][c4 * 4 + 2];
            float z3 = zs[j][c4 * 4 + 3];
#pragma unroll
            for (int h = 0; h < Hh; h++) {
                float4 w = ws4[h][wbase + c4];
                acc[h] += z0 * w.x + z1 * w.y + z2 * w.z + z3 * w.w;
            }
        }
    }

    const float k13 = 0.57735026918962576f; // sqrt(1/3)
#pragma unroll
    for (int h = 0; h < Hh; h++)
        g_a[(((long)h << 9) + i) * 512 + j0 + j] = k13 * (acc[h] + bbs[h]);
}

// ---------------- fused logits + softmax ------------------------------------
// block owns (h, 8 i-rows, all 512 j). warp w owns row i0+w; lane covers j = lane+32q.
// a = softmax( qk*s + b + pt + mask ) written back to g_a.
__global__ __launch_bounds__(256)
void logits_softmax_kernel(const float* __restrict__ mask, const float* __restrict__ head_w) {
    const int h = blockIdx.y;
    const int i0 = blockIdx.x * 8;
    const int t = threadIdx.x;
    const int ti = t >> 5;    // row within tile (= warp id)
    const int lane = t & 31;

    __shared__ float ks[256][17];
    __shared__ float kps[256][13];
    __shared__ float mj[256];
    __shared__ float qs[8][16];
    __shared__ float qps[8][12];
    __shared__ float mi[8];

    // q-side loads (once)
    if (t < 128) {
        int r = t >> 4, d = t & 15;
        qs[r][d] = g_proj[(long)(i0 + r) * NPROJ + h * 16 + d];
    } else if (t < 224) {
        int u = t - 128;
        int r = u / 12, d = u % 12;
        qps[r][d] = g_qpts[(i0 + r) * 144 + h * 12 + d];
    } else if (t < 232) {
        mi[t - 224] = mask[i0 + (t - 224)];
    }

    float x = head_w[h];
    float sp = (x > 20.f) ? x : log1pf(expf(x));
    const float hw = sp * 0.13608276348795434f;   // sqrt(1/54)
    const float kqk = 0.14433756729740643f;       // sqrt(1/48)

    float v[16];
    const long rowBase = (((long)h << 9) + i0 + ti) * 512;

    for (int jc = 0; jc < 2; jc++) {
        const int jbase = jc * 256;
        __syncthreads();
        for (int idx = t; idx < 256 * 16; idx += 256) {
            int r = idx >> 4, d = idx & 15;
            ks[r][d] = g_proj[(long)(jbase + r) * NPROJ + 192 + h * 32 + d];
        }
        for (int idx = t; idx < 256 * 12; idx += 256) {
            int r = idx / 12, d = idx % 12;
            kps[r][d] = g_kpts[(jbase + r) * 144 + h * 12 + d];
        }
        if (t < 256) mj[t] = mask[jbase + t];
        __syncthreads();

#pragma unroll
        for (int q = 0; q < 8; q++) {
            const int r = lane + q * 32;   // j within chunk
            float dot = 0.f;
#pragma unroll
            for (int d = 0; d < 16; d++) dot += qs[ti][d] * ks[r][d];
            float pt = 0.f;
#pragma unroll
            for (int pc = 0; pc < 12; pc++) {
                float df = qps[ti][pc] - kps[r][pc];
                pt += df * df;
            }
            float b = g_a[rowBase + jbase + r];
            v[jc * 8 + q] = dot * kqk + b - 0.5f * hw * pt
                          + 100000.0f * (mi[ti] * mj[r] - 1.0f);
        }
    }

    // per-row (per-warp) softmax over the 16 register values x 32 lanes
    float m = v[0];
#pragma unroll
    for (int q = 1; q < 16; q++) m = fmaxf(m, v[q]);
#pragma unroll
    for (int o = 16; o; o >>= 1) m = fmaxf(m, __shfl_xor_sync(0xffffffffu, m, o));

    float s = 0.f;
#pragma unroll
    for (int q = 0; q < 16; q++) { v[q] = expf(v[q] - m); s += v[q]; }
#pragma unroll
    for (int o = 16; o; o >>= 1) s += __shfl_xor_sync(0xffffffffu, s, o);
    const float inv = 1.f / s;

#pragma unroll
    for (int q = 0; q < 16; q++) {
        int j = (q >> 3) * 256 + (q & 7) * 32 + lane;
        g_a[rowBase + j] = v[q] * inv;
    }
}

// ---------------- o_pair[i,h,c] = sum_j a[h,i,j] * z[i,j,c] -> cat ----------
__global__ __launch_bounds__(256)
void opair_kernel(const float* __restrict__ z) {
    const int i = blockIdx.x;
    __shared__ __align__(16) float sa[12][512];
    __shared__ __align__(16) float zs[32][128];
    const int t = threadIdx.x; // 256

    for (int idx = t; idx < 12 * 512; idx += 256) {
        int h = idx >> 9, j = idx & 511;
        sa[h][j] = g_a[(((long)h << 9) + i) * 512 + j];
    }

    const int c = t & 127;
    const int hh = t >> 7; // 0/1 -> heads hh*6 .. +5
    float acc[6] = {0.f, 0.f, 0.f, 0.f, 0.f, 0.f};

    for (int j0 = 0; j0 < 512; j0 += 32) {
        __syncthreads();
        for (int idx = t; idx < 32 * 128; idx += 256) {
            int r = idx >> 7, cc = idx & 127;
            zs[r][cc] = z[(((long)i << 9) + j0 + r) * 128 + cc];
        }
        __syncthreads();
#pragma unroll
        for (int r4 = 0; r4 < 8; r4++) {
            float z0 = zs[r4 * 4 + 0][c];
            float z1 = zs[r4 * 4 + 1][c];
            float z2 = zs[r4 * 4 + 2][c];
            float z3 = zs[r4 * 4 + 3][c];
#pragma unroll
            for (int q = 0; q < 6; q++) {
                float4 s4 = *(const float4*)&sa[hh * 6 + q][j0 + r4 * 4];
                acc[q] += s4.x * z0 + s4.y * z1 + s4.z * z2 + s4.w * z3;
            }
        }
    }
#pragma unroll
    for (int q = 0; q < 6; q++)
        g_cat[(long)i * 2112 + 576 + (hh * 6 + q) * 128 + c] = acc[q];
}

// ---------------- assemble: o copy + inverse-frame o_pt + norms -------------
__global__ void assemble_kernel(const float* __restrict__ rot, const float* __restrict__ trans) {
    const int i = blockIdx.x;
    const int t = threadIdx.x; // 192
    __shared__ float R[9], T[3];
    if (t < 9) R[t] = rot[i * 9 + t];
    if (t < 3) T[t] = trans[i * 3 + t];
    __syncthreads();

    { // o copy: t = h*16+d
        int h = t >> 4, d = t & 15;
        g_cat[(long)i * 2112 + t] = g_o1[((long)h * NN + i) * 40 + d];
    }
    if (t < 96) { // point t = h*8+p
        int h = t >> 3, p = t & 7;
        const float* src = &g_o1[((long)h * NN + i) * 40 + 16 + p * 3];
        float w0 = src[0] - T[0];
        float w1 = src[1] - T[1];
        float w2 = src[2] - T[2];
        float l0 = R[0] * w0 + R[3] * w1 + R[6] * w2;
        float l1 = R[1] * w0 + R[4] * w1 + R[7] * w2;
        float l2 = R[2] * w0 + R[5] * w1 + R[8] * w2;
        g_cat[(long)i * 2112 + 192 + t] = l0;
        g_cat[(long)i * 2112 + 288 + t] = l1;
        g_cat[(long)i * 2112 + 384 + t] = l2;
        g_cat[(long)i * 2112 + 480 + t] = sqrtf(l0 * l0 + l1 * l1 + l2 * l2 + 1e-8f);
    }
}

// ---------------- launch ----------------------------------------------------
extern "C" void kernel_launch(void* const* d_in, const int* in_sizes, int n_in,
                              void* d_out, int out_size) {
    const float* s     = (const float*)d_in[0];
    const float* z     = (const float*)d_in[1];
    const float* rot   = (const float*)d_in[2];
    const float* trans = (const float*)d_in[3];
    const float* mask  = (const float*)d_in[4];
    const float* Wq    = (const float*)d_in[5];
    const float* bq    = (const float*)d_in[6];
    const float* Wkv   = (const float*)d_in[7];
    const float* bkv   = (const float*)d_in[8];
    const float* Wqp   = (const float*)d_in[9];
    const float* bqp   = (const float*)d_in[10];
    const float* Wkvp  = (const float*)d_in[11];
    const float* bkvp  = (const float*)d_in[12];
    const float* Wb    = (const float*)d_in[13];
    const float* bb    = (const float*)d_in[14];
    const float* head_w= (const float*)d_in[15];
    const float* Wout  = (const float*)d_in[16];
    const float* bout  = (const float*)d_in[17];
    float* out = (float*)d_out;

    float *pW, *pBias, *pProj, *pA, *pVcat, *pO1, *pCat;
    cudaGetSymbolAddress((void**)&pW, g_W);
    cudaGetSymbolAddress((void**)&pBias, g_bias);
    cudaGetSymbolAddress((void**)&pProj, g_proj);
    cudaGetSymbolAddress((void**)&pA, g_a);
    cudaGetSymbolAddress((void**)&pVcat, g_vcat);
    cudaGetSymbolAddress((void**)&pO1, g_o1);
    cudaGetSymbolAddress((void**)&pCat, g_cat);

    // pack fused projection weights (1024x1152) + bias
    pack_kernel<<<(CS * NPROJ + 255) / 256, 256>>>(Wq, Wkv, Wqp, Wkvp, bq, bkv, bqp, bkvp);

    // fused projection: s(512x1024) @ W(1024x1152) + bias -> g_proj
    gemm64<true><<<dim3(NPROJ / 64, 8, 1), 256>>>(s, pW, pBias, pProj, 512, 1024, NPROJ, 0, 0, 0);

    pts_kernel<<<512, 384>>>(rot, trans);
    bz_kernel<<<dim3(2, 512), 256>>>(z, Wb, bb);
    logits_softmax_kernel<<<dim3(64, 12), 256>>>(mask, head_w);

    // per-head: [a(512x512)] @ [v|v_pts](512x40) -> o1
    gemm64<false><<<dim3(1, 8, 12), 256>>>(pA, pVcat, nullptr, pO1, 512, 512, 40,
                                           (long)512 * 512, (long)512 * 40, (long)512 * 40);
    opair_kernel<<<512, 256>>>(z);
    assemble_kernel<<<512, 192>>>(rot, trans);

    // final: cat(512x2112) @ Wout(2112x1024) + bout -> out
    gemm64<true><<<dim3(16, 8, 1), 256>>>(pCat, Wout, bout, out, 512, 2112, 1024, 0, 0, 0);
}

// round 10
// speedup vs baseline: 1.7321x; 1.0411x over previous
#include <cuda_runtime.h>
#include <cuda_bf16.h>
#include <math.h>
#include <stdint.h>

#define NN 512
#define CS 1024
#define CZd 128
#define Hh 12
#define HDd 16
#define PQp 4
#define PVp 8
#define NPROJ 1152   // 192 q | 384 kv | 144 qp | 432 kvp
#define KCAT 2112

// ---------------- scratch (device globals; no allocation allowed) ----------
__device__ __align__(16) float g_bias[NPROJ];
__device__ __align__(16) float g_proj[NN * NPROJ];
__device__ __align__(16) float g_qpts[NN * Hh * PQp * 3];
__device__ __align__(16) float g_kpts[NN * Hh * PQp * 3];
__device__ __align__(16) float g_vcat[Hh * NN * 40];
__device__ __align__(16) float g_a[Hh * NN * NN];
__device__ __align__(16) float g_o1[Hh * NN * 40];
__device__ __align__(16) float g_cat[NN * KCAT];

// bf16 split operands for tensor-core GEMMs
__device__ __align__(16) __nv_bfloat16 g_sh[NN * CS];
__device__ __align__(16) __nv_bfloat16 g_sl[NN * CS];
__device__ __align__(16) __nv_bfloat16 g_Wth[NPROJ * CS];   // W^T [n][k] K-major
__device__ __align__(16) __nv_bfloat16 g_Wtl[NPROJ * CS];
__device__ __align__(16) __nv_bfloat16 g_WoTh[1024 * KCAT]; // Wout^T [n][k]
__device__ __align__(16) __nv_bfloat16 g_WoTl[1024 * KCAT];
__device__ __align__(16) __nv_bfloat16 g_cath[NN * KCAT];
__device__ __align__(16) __nv_bfloat16 g_catl[NN * KCAT];

// ---------------- warp-level bf16 MMA (baseline PTX, works on sm_103) -------
__device__ __forceinline__ void mma16816(float* c, const uint32_t* a, const uint32_t* b) {
    asm volatile(
        "mma.sync.aligned.m16n8k16.row.col.f32.bf16.bf16.f32 "
        "{%0,%1,%2,%3}, {%4,%5,%6,%7}, {%8,%9}, {%0,%1,%2,%3};"
        : "+f"(c[0]), "+f"(c[1]), "+f"(c[2]), "+f"(c[3])
        : "r"(a[0]), "r"(a[1]), "r"(a[2]), "r"(a[3]), "r"(b[0]), "r"(b[1]));
}

// ---------------- hgemm: C = A @ B^T, split-bf16, HMMA ----------------------
// A: [M][K] bf16 hi/lo (K contiguous). B: [Nw][K] bf16 hi/lo (K contiguous).
// C: fp32 [M][Nw] (+bias). M%64==0, Nw%64==0, K%32==0.
// grid (Nw/64, M/64), block 256 (8 warps: 4 m-bands x 2 n-bands).
template <bool HAS_BIAS>
__global__ __launch_bounds__(256)
void hgemm(const __nv_bfloat16* __restrict__ Ah, const __nv_bfloat16* __restrict__ Al,
           const __nv_bfloat16* __restrict__ Bh, const __nv_bfloat16* __restrict__ Bl,
           const float* __restrict__ bias, float* __restrict__ C,
           int M, int K, int Nw) {
    // padded stride 20 words (40 bf16): conflict-free fragment loads
    __shared__ __align__(16) uint32_t sAh[64 * 20], sAl[64 * 20];
    __shared__ __align__(16) uint32_t sBh[64 * 20], sBl[64 * 20];

    const int t = threadIdx.x;
    const int wid = t >> 5, lane = t & 31;
    const int wm = wid >> 1;      // 0..3 -> rows 16*wm
    const int wn = wid & 1;       // 0..1 -> cols 32*wn
    const int lr = lane >> 2, lc = lane & 3;
    const int m0 = blockIdx.y * 64, n0 = blockIdx.x * 64;
    const int K2 = K >> 1;        // words per row

    const uint32_t* Ah32 = (const uint32_t*)Ah;
    const uint32_t* Al32 = (const uint32_t*)Al;
    const uint32_t* Bh32 = (const uint32_t*)Bh;
    const uint32_t* Bl32 = (const uint32_t*)Bl;

    float acc[4][4];
#pragma unroll
    for (int j = 0; j < 4; j++)
#pragma unroll
        for (int r = 0; r < 4; r++) acc[j][r] = 0.f;

    for (int kw = 0; kw < K2; kw += 16) {   // 32 bf16 per chunk
        __syncthreads();
        for (int idx = t; idx < 1024; idx += 256) {
            int r = idx >> 4, w = idx & 15;
            long aoff = (long)(m0 + r) * K2 + kw + w;
            long boff = (long)(n0 + r) * K2 + kw + w;
            sAh[r * 20 + w] = Ah32[aoff];
            sAl[r * 20 + w] = Al32[aoff];
            sBh[r * 20 + w] = Bh32[boff];
            sBl[r * 20 + w] = Bl32[boff];
        }
        __syncthreads();

#pragma unroll
        for (int ks = 0; ks < 2; ks++) {
            const int kb = ks * 8;
            uint32_t ah[4], al[4];
            const int ar0 = (16 * wm + lr) * 20 + kb + lc;
            const int ar1 = ar0 + 8 * 20;
            ah[0] = sAh[ar0]; ah[1] = sAh[ar1]; ah[2] = sAh[ar0 + 4]; ah[3] = sAh[ar1 + 4];
            al[0] = sAl[ar0]; al[1] = sAl[ar1]; al[2] = sAl[ar0 + 4]; al[3] = sAl[ar1 + 4];
#pragma unroll
            for (int j = 0; j < 4; j++) {
                const int br0 = (32 * wn + 8 * j + lr) * 20 + kb + lc;
                uint32_t bh[2] = {sBh[br0], sBh[br0 + 4]};
                uint32_t bl[2] = {sBl[br0], sBl[br0 + 4]};
                mma16816(acc[j], ah, bh);
                mma16816(acc[j], ah, bl);
                mma16816(acc[j], al, bh);
            }
        }
    }

    const int mrow = m0 + 16 * wm + lr;
#pragma unroll
    for (int j = 0; j < 4; j++) {
        const int n = n0 + 32 * wn + 8 * j + lc * 2;
        float b0 = HAS_BIAS ? bias[n] : 0.f;
        float b1 = HAS_BIAS ? bias[n + 1] : 0.f;
        C[(long)mrow * Nw + n] = acc[j][0] + b0;
        C[(long)mrow * Nw + n + 1] = acc[j][1] + b1;
        C[(long)(mrow + 8) * Nw + n] = acc[j][2] + b0;
        C[(long)(mrow + 8) * Nw + n + 1] = acc[j][3] + b1;
    }
}

// ---------------- conversions / transposes ----------------------------------
__global__ void conv_hl_kernel(const float* __restrict__ src, __nv_bfloat16* __restrict__ dh,
                               __nv_bfloat16* __restrict__ dl, int n) {
    int idx = blockIdx.x * 256 + threadIdx.x;
    if (idx < n) {
        float v = src[idx];
        __nv_bfloat16 hi = __float2bfloat16(v);
        dh[idx] = hi;
        dl[idx] = __float2bfloat16(v - __bfloat162float(hi));
    }
}

// pack+transpose+convert proj weights: virtual W[k=1024][c=1152] -> g_Wt[c][k]
__global__ void packWT_kernel(const float* __restrict__ Wq, const float* __restrict__ Wkv,
                              const float* __restrict__ Wqp, const float* __restrict__ Wkvp) {
    __shared__ float sm[32][33];
    const int c0 = blockIdx.x * 32, k0 = blockIdx.y * 32;
    const int tx = threadIdx.x, ty = threadIdx.y;
#pragma unroll
    for (int rr = 0; rr < 4; rr++) {
        int k = k0 + ty + rr * 8;
        int c = c0 + tx;
        float v;
        if (c < 192) v = Wq[k * 192 + c];
        else if (c < 576) v = Wkv[k * 384 + (c - 192)];
        else if (c < 720) v = Wqp[k * 144 + (c - 576)];
        else v = Wkvp[k * 432 + (c - 720)];
        sm[ty + rr * 8][tx] = v;
    }
    __syncthreads();
#pragma unroll
    for (int rr = 0; rr < 4; rr++) {
        int c = c0 + ty + rr * 8;
        int k = k0 + tx;
        float v = sm[tx][ty + rr * 8];
        __nv_bfloat16 hi = __float2bfloat16(v);
        g_Wth[(long)c * CS + k] = hi;
        g_Wtl[(long)c * CS + k] = __float2bfloat16(v - __bfloat162float(hi));
    }
}

// transpose+convert Wout[2112][1024] -> g_WoT[1024][2112]
__global__ void WoutT_kernel(const float* __restrict__ Wout) {
    __shared__ float sm[32][33];
    const int n0 = blockIdx.x * 32, k0 = blockIdx.y * 32;
    const int tx = threadIdx.x, ty = threadIdx.y;
#pragma unroll
    for (int rr = 0; rr < 4; rr++)
        sm[ty + rr * 8][tx] = Wout[(long)(k0 + ty + rr * 8) * 1024 + n0 + tx];
    __syncthreads();
#pragma unroll
    for (int rr = 0; rr < 4; rr++) {
        int n = n0 + ty + rr * 8;
        int k = k0 + tx;
        float v = sm[tx][ty + rr * 8];
        __nv_bfloat16 hi = __float2bfloat16(v);
        g_WoTh[(long)n * KCAT + k] = hi;
        g_WoTl[(long)n * KCAT + k] = __float2bfloat16(v - __bfloat162float(hi));
    }
}

__global__ void packbias_kernel(const float* __restrict__ bq, const float* __restrict__ bkv,
                                const float* __restrict__ bqp, const float* __restrict__ bkvp) {
    int c = blockIdx.x * 256 + threadIdx.x;
    if (c < NPROJ) {
        float v;
        if (c < 192) v = bq[c];
        else if (c < 576) v = bkv[c - 192];
        else if (c < 720) v = bqp[c - 576];
        else v = bkvp[c - 720];
        g_bias[c] = v;
    }
}

// ---------------- fp32 SGEMM (kept for a @ vcat) ----------------------------
template <bool HAS_BIAS>
__global__ __launch_bounds__(256)
void gemm64(const float* __restrict__ A, const float* __restrict__ Bm,
            const float* __restrict__ bias, float* __restrict__ C,
            int M, int K, int Nw, long sA, long sB, long sC) {
    A += blockIdx.z * sA;
    Bm += blockIdx.z * sB;
    C += blockIdx.z * sC;

    __shared__ __align__(16) float As[2][16][68];
    __shared__ __align__(16) float Bs[2][16][64];

    const int tid = threadIdx.x;
    const int m0 = blockIdx.y * 64;
    const int n0 = blockIdx.x * 64;

    const int aRow = tid >> 2;
    const int aCol = (tid & 3) * 4;
    const int bRow = tid >> 4;
    const int bCol = (tid & 15) * 4;
    const int tm = tid >> 4;
    const int tn = tid & 15;

    const float* Ag = A + (long)(m0 + aRow) * K + aCol;
    const float* Bg = Bm + (long)bRow * Nw + n0 + bCol;
    const bool bPred = (n0 + bCol + 3) < Nw;

    float4 ra = *(const float4*)Ag;
    float4 rb = bPred ? *(const float4*)Bg : make_float4(0.f, 0.f, 0.f, 0.f);
    As[0][aCol + 0][aRow] = ra.x;
    As[0][aCol + 1][aRow] = ra.y;
    As[0][aCol + 2][aRow] = ra.z;
    As[0][aCol + 3][aRow] = ra.w;
    *(float4*)&Bs[0][bRow][bCol] = rb;
    __syncthreads();

    float acc[4][4];
#pragma unroll
    for (int r = 0; r < 4; r++)
#pragma unroll
        for (int c = 0; c < 4; c++) acc[r][c] = 0.f;

    const int T = K >> 4;
    for (int t = 0; t < T; t++) {
        const int cur = t & 1;
        if (t + 1 < T) {
            ra = *(const float4*)(Ag + (t + 1) * 16);
            rb = bPred ? *(const float4*)(Bg + (long)(t + 1) * 16 * Nw)
                       : make_float4(0.f, 0.f, 0.f, 0.f);
        }
#pragma unroll
        for (int kk = 0; kk < 16; kk++) {
            float4 a4 = *(const float4*)&As[cur][kk][tm * 4];
            float4 b4 = *(const float4*)&Bs[cur][kk][tn * 4];
            float ar[4] = {a4.x, a4.y, a4.z, a4.w};
            float br[4] = {b4.x, b4.y, b4.z, b4.w};
#pragma unroll
            for (int r = 0; r < 4; r++)
#pragma unroll
                for (int c = 0; c < 4; c++) acc[r][c] += ar[r] * br[c];
        }
        if (t + 1 < T) {
            const int nxt = cur ^ 1;
            As[nxt][aCol + 0][aRow] = ra.x;
            As[nxt][aCol + 1][aRow] = ra.y;
            As[nxt][aCol + 2][aRow] = ra.z;
            As[nxt][aCol + 3][aRow] = ra.w;
            *(float4*)&Bs[nxt][bRow][bCol] = rb;
            __syncthreads();
        }
    }

#pragma unroll
    for (int r = 0; r < 4; r++) {
        const int m = m0 + tm * 4 + r;
#pragma unroll
        for (int c = 0; c < 4; c++) {
            const int n = n0 + tn * 4 + c;
            if (n < Nw) {
                float v = acc[r][c];
                if (HAS_BIAS) v += bias[n];
                C[(long)m * Nw + n] = v;
            }
        }
    }
}

// ---------------- point transform + vcat fill -------------------------------
__global__ void pts_kernel(const float* __restrict__ rot, const float* __restrict__ trans) {
    const int i = blockIdx.x;
    const int t = threadIdx.x; // 384
    __shared__ float R[9], T[3];
    if (t < 9) R[t] = rot[i * 9 + t];
    if (t < 3) T[t] = trans[i * 3 + t];
    __syncthreads();

    const float* P = g_proj + (long)i * NPROJ;

    if (t < 48) {
        float l0 = P[576 + 0 * 48 + t];
        float l1 = P[576 + 1 * 48 + t];
        float l2 = P[576 + 2 * 48 + t];
#pragma unroll
        for (int ci = 0; ci < 3; ci++)
            g_qpts[i * 144 + 3 * t + ci] =
                R[ci * 3 + 0] * l0 + R[ci * 3 + 1] * l1 + R[ci * 3 + 2] * l2 + T[ci];
    } else if (t < 96) {
        int u = t - 48;
        int h = u >> 2, p = u & 3;
        int pidx = h * 12 + p;
        float l0 = P[720 + 0 * 144 + pidx];
        float l1 = P[720 + 1 * 144 + pidx];
        float l2 = P[720 + 2 * 144 + pidx];
#pragma unroll
        for (int ci = 0; ci < 3; ci++)
            g_kpts[i * 144 + 3 * u + ci] =
                R[ci * 3 + 0] * l0 + R[ci * 3 + 1] * l1 + R[ci * 3 + 2] * l2 + T[ci];
    } else if (t < 192) {
        int u = t - 96;
        int h = u >> 3, p = u & 7;
        int pidx = h * 12 + 4 + p;
        float l0 = P[720 + 0 * 144 + pidx];
        float l1 = P[720 + 1 * 144 + pidx];
        float l2 = P[720 + 2 * 144 + pidx];
#pragma unroll
        for (int ci = 0; ci < 3; ci++)
            g_vcat[((long)h * NN + i) * 40 + 16 + p * 3 + ci] =
                R[ci * 3 + 0] * l0 + R[ci * 3 + 1] * l1 + R[ci * 3 + 2] * l2 + T[ci];
    } else {
        int u = t - 192;
        int h = u >> 4, d = u & 15;
        g_vcat[((long)h * NN + i) * 40 + d] = P[192 + h * 32 + 16 + d];
    }
}

// ---------------- b = sqrt(1/3) * (z @ Wb + bb) -> g_a ----------------------
// v3: 2 j-rows/thread (j = t, t+256), c-chunks of 16.
__global__ __launch_bounds__(256)
void bz_kernel(const float* __restrict__ z, const float* __restrict__ Wb,
               const float* __restrict__ bb) {
    __shared__ float4 ws4[Hh][32];
    __shared__ float bbs[Hh];
    __shared__ float zs[512][17];

    const int i = blockIdx.x;
    const int t = threadIdx.x;

    for (int idx = t; idx < Hh * 32; idx += 256) {
        int h = idx >> 5, c4 = idx & 31;
        ws4[h][c4] = make_float4(Wb[(c4 * 4 + 0) * Hh + h], Wb[(c4 * 4 + 1) * Hh + h],
                                 Wb[(c4 * 4 + 2) * Hh + h], Wb[(c4 * 4 + 3) * Hh + h]);
    }
    if (t < Hh) bbs[t] = bb[t];

    float acc0[Hh], acc1[Hh];
#pragma unroll
    for (int h = 0; h < Hh; h++) { acc0[h] = 0.f; acc1[h] = 0.f; }

    for (int c0 = 0; c0 < 128; c0 += 16) {
        __syncthreads();
        for (int idx = t; idx < 2048; idx += 256) {
            int r = idx >> 2, c4 = idx & 3;
            float4 v = *(const float4*)&z[((long)i * 512 + r) * 128 + c0 + c4 * 4];
            zs[r][c4 * 4 + 0] = v.x;
            zs[r][c4 * 4 + 1] = v.y;
            zs[r][c4 * 4 + 2] = v.z;
            zs[r][c4 * 4 + 3] = v.w;
        }
        __syncthreads();

        const int wb = c0 >> 2;
#pragma unroll
        for (int c4 = 0; c4 < 4; c4++) {
            float a0 = zs[t][c4 * 4 + 0], a1 = zs[t][c4 * 4 + 1];
            float a2 = zs[t][c4 * 4 + 2], a3 = zs[t][c4 * 4 + 3];
            float b0 = zs[t + 256][c4 * 4 + 0], b1 = zs[t + 256][c4 * 4 + 1];
            float b2 = zs[t + 256][c4 * 4 + 2], b3 = zs[t + 256][c4 * 4 + 3];
#pragma unroll
            for (int h = 0; h < Hh; h++) {
                float4 w = ws4[h][wb + c4];
                acc0[h] += a0 * w.x + a1 * w.y + a2 * w.z + a3 * w.w;
                acc1[h] += b0 * w.x + b1 * w.y + b2 * w.z + b3 * w.w;
            }
        }
    }

    const float k13 = 0.57735026918962576f;
#pragma unroll
    for (int h = 0; h < Hh; h++) {
        g_a[(((long)h << 9) + i) * 512 + t] = k13 * (acc0[h] + bbs[h]);
        g_a[(((long)h << 9) + i) * 512 + t + 256] = k13 * (acc1[h] + bbs[h]);
    }
}

// ---------------- fused logits + softmax ------------------------------------
__global__ __launch_bounds__(256)
void logits_softmax_kernel(const float* __restrict__ mask, const float* __restrict__ head_w) {
    const int h = blockIdx.y;
    const int i0 = blockIdx.x * 8;
    const int t = threadIdx.x;
    const int ti = t >> 5;
    const int lane = t & 31;

    __shared__ float ks[256][17];
    __shared__ float kps[256][13];
    __shared__ float mj[256];
    __shared__ float qs[8][16];
    __shared__ float qps[8][12];
    __shared__ float mi[8];

    if (t < 128) {
        int r = t >> 4, d = t & 15;
        qs[r][d] = g_proj[(long)(i0 + r) * NPROJ + h * 16 + d];
    } else if (t < 224) {
        int u = t - 128;
        int r = u / 12, d = u % 12;
        qps[r][d] = g_qpts[(i0 + r) * 144 + h * 12 + d];
    } else if (t < 232) {
        mi[t - 224] = mask[i0 + (t - 224)];
    }

    float x = head_w[h];
    float sp = (x > 20.f) ? x : log1pf(expf(x));
    const float hw = sp * 0.13608276348795434f;
    const float kqk = 0.14433756729740643f;

    float v[16];
    const long rowBase = (((long)h << 9) + i0 + ti) * 512;

    for (int jc = 0; jc < 2; jc++) {
        const int jbase = jc * 256;
        __syncthreads();
        for (int idx = t; idx < 256 * 16; idx += 256) {
            int r = idx >> 4, d = idx & 15;
            ks[r][d] = g_proj[(long)(jbase + r) * NPROJ + 192 + h * 32 + d];
        }
        for (int idx = t; idx < 256 * 12; idx += 256) {
            int r = idx / 12, d = idx % 12;
            kps[r][d] = g_kpts[(jbase + r) * 144 + h * 12 + d];
        }
        if (t < 256) mj[t] = mask[jbase + t];
        __syncthreads();

#pragma unroll
        for (int q = 0; q < 8; q++) {
            const int r = lane + q * 32;
            float dot = 0.f;
#pragma unroll
            for (int d = 0; d < 16; d++) dot += qs[ti][d] * ks[r][d];
            float pt = 0.f;
#pragma unroll
            for (int pc = 0; pc < 12; pc++) {
                float df = qps[ti][pc] - kps[r][pc];
                pt += df * df;
            }
            float b = g_a[rowBase + jbase + r];
            v[jc * 8 + q] = dot * kqk + b - 0.5f * hw * pt
                          + 100000.0f * (mi[ti] * mj[r] - 1.0f);
        }
    }

    float m = v[0];
#pragma unroll
    for (int q = 1; q < 16; q++) m = fmaxf(m, v[q]);
#pragma unroll
    for (int o = 16; o; o >>= 1) m = fmaxf(m, __shfl_xor_sync(0xffffffffu, m, o));

    float s = 0.f;
#pragma unroll
    for (int q = 0; q < 16; q++) { v[q] = expf(v[q] - m); s += v[q]; }
#pragma unroll
    for (int o = 16; o; o >>= 1) s += __shfl_xor_sync(0xffffffffu, s, o);
    const float inv = 1.f / s;

#pragma unroll
    for (int q = 0; q < 16; q++) {
        int j = (q >> 3) * 256 + (q & 7) * 32 + lane;
        g_a[rowBase + j] = v[q] * inv;
    }
}

// ---------------- o_pair[i,h,c] = sum_j a[h,i,j] * z[i,j,c] -> cat ----------
__global__ __launch_bounds__(256)
void opair_kernel(const float* __restrict__ z) {
    const int i = blockIdx.x;
    __shared__ __align__(16) float sa[12][512];
    __shared__ __align__(16) float zs[32][128];
    const int t = threadIdx.x; // 256

    for (int idx = t; idx < 12 * 512; idx += 256) {
        int h = idx >> 9, j = idx & 511;
        sa[h][j] = g_a[(((long)h << 9) + i) * 512 + j];
    }

    const int c = t & 127;
    const int hh = t >> 7;
    float acc[6] = {0.f, 0.f, 0.f, 0.f, 0.f, 0.f};

    for (int j0 = 0; j0 < 512; j0 += 32) {
        __syncthreads();
        for (int idx = t; idx < 32 * 128; idx += 256) {
            int r = idx >> 7, cc = idx & 127;
            zs[r][cc] = z[(((long)i << 9) + j0 + r) * 128 + cc];
        }
        __syncthreads();
#pragma unroll
        for (int r4 = 0; r4 < 8; r4++) {
            float z0 = zs[r4 * 4 + 0][c];
            float z1 = zs[r4 * 4 + 1][c];
            float z2 = zs[r4 * 4 + 2][c];
            float z3 = zs[r4 * 4 + 3][c];
#pragma unroll
            for (int q = 0; q < 6; q++) {
                float4 s4 = *(const float4*)&sa[hh * 6 + q][j0 + r4 * 4];
                acc[q] += s4.x * z0 + s4.y * z1 + s4.z * z2 + s4.w * z3;
            }
        }
    }
#pragma unroll
    for (int q = 0; q < 6; q++)
        g_cat[(long)i * 2112 + 576 + (hh * 6 + q) * 128 + c] = acc[q];
}

// ---------------- assemble: o copy + inverse-frame o_pt + norms -------------
__global__ void assemble_kernel(const float* __restrict__ rot, const float* __restrict__ trans) {
    const int i = blockIdx.x;
    const int t = threadIdx.x; // 192
    __shared__ float R[9], T[3];
    if (t < 9) R[t] = rot[i * 9 + t];
    if (t < 3) T[t] = trans[i * 3 + t];
    __syncthreads();

    {
        int h = t >> 4, d = t & 15;
        g_cat[(long)i * 2112 + t] = g_o1[((long)h * NN + i) * 40 + d];
    }
    if (t < 96) {
        int h = t >> 3, p = t & 7;
        const float* src = &g_o1[((long)h * NN + i) * 40 + 16 + p * 3];
        float w0 = src[0] - T[0];
        float w1 = src[1] - T[1];
        float w2 = src[2] - T[2];
        float l0 = R[0] * w0 + R[3] * w1 + R[6] * w2;
        float l1 = R[1] * w0 + R[4] * w1 + R[7] * w2;
        float l2 = R[2] * w0 + R[5] * w1 + R[8] * w2;
        g_cat[(long)i * 2112 + 192 + t] = l0;
        g_cat[(long)i * 2112 + 288 + t] = l1;
        g_cat[(long)i * 2112 + 384 + t] = l2;
        g_cat[(long)i * 2112 + 480 + t] = sqrtf(l0 * l0 + l1 * l1 + l2 * l2 + 1e-8f);
    }
}

// ---------------- launch ----------------------------------------------------
extern "C" void kernel_launch(void* const* d_in, const int* in_sizes, int n_in,
                              void* d_out, int out_size) {
    const float* s     = (const float*)d_in[0];
    const float* z     = (const float*)d_in[1];
    const float* rot   = (const float*)d_in[2];
    const float* trans = (const float*)d_in[3];
    const float* mask  = (const float*)d_in[4];
    const float* Wq    = (const float*)d_in[5];
    const float* bq    = (const float*)d_in[6];
    const float* Wkv   = (const float*)d_in[7];
    const float* bkv   = (const float*)d_in[8];
    const float* Wqp   = (const float*)d_in[9];
    const float* bqp   = (const float*)d_in[10];
    const float* Wkvp  = (const float*)d_in[11];
    const float* bkvp  = (const float*)d_in[12];
    const float* Wb    = (const float*)d_in[13];
    const float* bb    = (const float*)d_in[14];
    const float* head_w= (const float*)d_in[15];
    const float* Wout  = (const float*)d_in[16];
    const float* bout  = (const float*)d_in[17];
    float* out = (float*)d_out;

    float *pBias, *pProj, *pA, *pVcat, *pO1, *pCat;
    __nv_bfloat16 *pSh, *pSl, *pWth, *pWtl, *pWoTh, *pWoTl, *pCath, *pCatl;
    cudaGetSymbolAddress((void**)&pBias, g_bias);
    cudaGetSymbolAddress((void**)&pProj, g_proj);
    cudaGetSymbolAddress((void**)&pA, g_a);
    cudaGetSymbolAddress((void**)&pVcat, g_vcat);
    cudaGetSymbolAddress((void**)&pO1, g_o1);
    cudaGetSymbolAddress((void**)&pCat, g_cat);
    cudaGetSymbolAddress((void**)&pSh, g_sh);
    cudaGetSymbolAddress((void**)&pSl, g_sl);
    cudaGetSymbolAddress((void**)&pWth, g_Wth);
    cudaGetSymbolAddress((void**)&pWtl, g_Wtl);
    cudaGetSymbolAddress((void**)&pWoTh, g_WoTh);
    cudaGetSymbolAddress((void**)&pWoTl, g_WoTl);
    cudaGetSymbolAddress((void**)&pCath, g_cath);
    cudaGetSymbolAddress((void**)&pCatl, g_catl);

    // operand prep
    conv_hl_kernel<<<(NN * CS + 255) / 256, 256>>>(s, pSh, pSl, NN * CS);
    packWT_kernel<<<dim3(NPROJ / 32, CS / 32), dim3(32, 8)>>>(Wq, Wkv, Wqp, Wkvp);
    packbias_kernel<<<(NPROJ + 255) / 256, 256>>>(bq, bkv, bqp, bkvp);
    WoutT_kernel<<<dim3(1024 / 32, KCAT / 32), dim3(32, 8)>>>(Wout);

    // fused projection on tensor cores (HMMA): s @ [Wq|Wkv|Wqp|Wkvp] + bias
    hgemm<true><<<dim3(NPROJ / 64, NN / 64), 256>>>(pSh, pSl, pWth, pWtl, pBias, pProj,
                                                    NN, CS, NPROJ);

    pts_kernel<<<512, 384>>>(rot, trans);
    bz_kernel<<<512, 256>>>(z, Wb, bb);
    logits_softmax_kernel<<<dim3(64, 12), 256>>>(mask, head_w);

    // per-head: a(512x512) @ [v|v_pts](512x40) -> o1 (fp32)
    gemm64<false><<<dim3(1, 8, 12), 256>>>(pA, pVcat, nullptr, pO1, 512, 512, 40,
                                           (long)512 * 512, (long)512 * 40, (long)512 * 40);
    opair_kernel<<<512, 256>>>(z);
    assemble_kernel<<<512, 192>>>(rot, trans);

    // final on tensor cores (HMMA): cat(512x2112) @ Wout(2112x1024) + bout
    conv_hl_kernel<<<(NN * KCAT + 255) / 256, 256>>>(pCat, pCath, pCatl, NN * KCAT);
    hgemm<true><<<dim3(1024 / 64, NN / 64), 256>>>(pCath, pCatl, pWoTh, pWoTl, bout, out,
                                                   NN, KCAT, 1024);
}

// round 11
// speedup vs baseline: 1.9529x; 1.1275x over previous
#include <cuda_runtime.h>
#include <cuda_bf16.h>
#include <math.h>
#include <stdint.h>

#define NN 512
#define CS 1024
#define CZd 128
#define Hh 12
#define HDd 16
#define PQp 4
#define PVp 8
#define NPROJ 1152   // 192 q | 384 kv | 144 qp | 432 kvp
#define KCAT 2112

// ---------------- scratch (device globals; no allocation allowed) ----------
__device__ __align__(16) float g_bias[NPROJ];
__device__ __align__(16) float g_proj[NN * NPROJ];
__device__ __align__(16) float g_qpts[NN * Hh * PQp * 3];
__device__ __align__(16) float g_kpts[NN * Hh * PQp * 3];
__device__ __align__(16) float g_vcat[Hh * NN * 40];
__device__ __align__(16) float g_a[Hh * NN * NN];
__device__ __align__(16) float g_o1[Hh * NN * 40];

// bf16 split operands for tensor-core GEMMs
__device__ __align__(16) __nv_bfloat16 g_sh[NN * CS];
__device__ __align__(16) __nv_bfloat16 g_sl[NN * CS];
__device__ __align__(16) __nv_bfloat16 g_Wth[NPROJ * CS];   // W^T [n][k] K-major
__device__ __align__(16) __nv_bfloat16 g_Wtl[NPROJ * CS];
__device__ __align__(16) __nv_bfloat16 g_WoTh[1024 * KCAT]; // Wout^T [n][k]
__device__ __align__(16) __nv_bfloat16 g_WoTl[1024 * KCAT];
__device__ __align__(16) __nv_bfloat16 g_cath[NN * KCAT];
__device__ __align__(16) __nv_bfloat16 g_catl[NN * KCAT];

// ---------------- warp-level bf16 MMA (baseline PTX, works on sm_103) -------
__device__ __forceinline__ void mma16816(float* c, const uint32_t* a, const uint32_t* b) {
    asm volatile(
        "mma.sync.aligned.m16n8k16.row.col.f32.bf16.bf16.f32 "
        "{%0,%1,%2,%3}, {%4,%5,%6,%7}, {%8,%9}, {%0,%1,%2,%3};"
        : "+f"(c[0]), "+f"(c[1]), "+f"(c[2]), "+f"(c[3])
        : "r"(a[0]), "r"(a[1]), "r"(a[2]), "r"(a[3]), "r"(b[0]), "r"(b[1]));
}

__device__ __forceinline__ void split_store(float v, __nv_bfloat16* dh, __nv_bfloat16* dl) {
    __nv_bfloat16 hi = __float2bfloat16(v);
    *dh = hi;
    *dl = __float2bfloat16(v - __bfloat162float(hi));
}

// ---------------- hgemm: C = A @ B^T, split-bf16, HMMA ----------------------
// A: [M][K] bf16 hi/lo (K contiguous). B: [Nw][K] bf16 hi/lo (K contiguous).
// C: fp32 [M][Nw] (+bias). M%64==0, Nw%64==0, K%32==0.
// grid (Nw/64, M/64), block 256 (8 warps: 4 m-bands x 2 n-bands).
template <bool HAS_BIAS>
__global__ __launch_bounds__(256)
void hgemm(const __nv_bfloat16* __restrict__ Ah, const __nv_bfloat16* __restrict__ Al,
           const __nv_bfloat16* __restrict__ Bh, const __nv_bfloat16* __restrict__ Bl,
           const float* __restrict__ bias, float* __restrict__ C,
           int M, int K, int Nw) {
    __shared__ __align__(16) uint32_t sAh[64 * 20], sAl[64 * 20];
    __shared__ __align__(16) uint32_t sBh[64 * 20], sBl[64 * 20];

    const int t = threadIdx.x;
    const int wid = t >> 5, lane = t & 31;
    const int wm = wid >> 1;
    const int wn = wid & 1;
    const int lr = lane >> 2, lc = lane & 3;
    const int m0 = blockIdx.y * 64, n0 = blockIdx.x * 64;
    const int K2 = K >> 1;

    const uint32_t* Ah32 = (const uint32_t*)Ah;
    const uint32_t* Al32 = (const uint32_t*)Al;
    const uint32_t* Bh32 = (const uint32_t*)Bh;
    const uint32_t* Bl32 = (const uint32_t*)Bl;

    float acc[4][4];
#pragma unroll
    for (int j = 0; j < 4; j++)
#pragma unroll
        for (int r = 0; r < 4; r++) acc[j][r] = 0.f;

    for (int kw = 0; kw < K2; kw += 16) {
        __syncthreads();
        for (int idx = t; idx < 1024; idx += 256) {
            int r = idx >> 4, w = idx & 15;
            long aoff = (long)(m0 + r) * K2 + kw + w;
            long boff = (long)(n0 + r) * K2 + kw + w;
            sAh[r * 20 + w] = Ah32[aoff];
            sAl[r * 20 + w] = Al32[aoff];
            sBh[r * 20 + w] = Bh32[boff];
            sBl[r * 20 + w] = Bl32[boff];
        }
        __syncthreads();

#pragma unroll
        for (int ks = 0; ks < 2; ks++) {
            const int kb = ks * 8;
            uint32_t ah[4], al[4];
            const int ar0 = (16 * wm + lr) * 20 + kb + lc;
            const int ar1 = ar0 + 8 * 20;
            ah[0] = sAh[ar0]; ah[1] = sAh[ar1]; ah[2] = sAh[ar0 + 4]; ah[3] = sAh[ar1 + 4];
            al[0] = sAl[ar0]; al[1] = sAl[ar1]; al[2] = sAl[ar0 + 4]; al[3] = sAl[ar1 + 4];
#pragma unroll
            for (int j = 0; j < 4; j++) {
                const int br0 = (32 * wn + 8 * j + lr) * 20 + kb + lc;
                uint32_t bh[2] = {sBh[br0], sBh[br0 + 4]};
                uint32_t bl[2] = {sBl[br0], sBl[br0 + 4]};
                mma16816(acc[j], ah, bh);
                mma16816(acc[j], ah, bl);
                mma16816(acc[j], al, bh);
            }
        }
    }

    const int mrow = m0 + 16 * wm + lr;
#pragma unroll
    for (int j = 0; j < 4; j++) {
        const int n = n0 + 32 * wn + 8 * j + lc * 2;
        float b0 = HAS_BIAS ? bias[n] : 0.f;
        float b1 = HAS_BIAS ? bias[n + 1] : 0.f;
        C[(long)mrow * Nw + n] = acc[j][0] + b0;
        C[(long)mrow * Nw + n + 1] = acc[j][1] + b1;
        C[(long)(mrow + 8) * Nw + n] = acc[j][2] + b0;
        C[(long)(mrow + 8) * Nw + n + 1] = acc[j][3] + b1;
    }
}

// ---------------- conversions / transposes ----------------------------------
__global__ void conv_hl_kernel(const float* __restrict__ src, __nv_bfloat16* __restrict__ dh,
                               __nv_bfloat16* __restrict__ dl, int n) {
    int idx = blockIdx.x * 256 + threadIdx.x;
    if (idx < n) split_store(src[idx], dh + idx, dl + idx);
}

// pack+transpose+convert proj weights: virtual W[k=1024][c=1152] -> g_Wt[c][k]
__global__ void packWT_kernel(const float* __restrict__ Wq, const float* __restrict__ Wkv,
                              const float* __restrict__ Wqp, const float* __restrict__ Wkvp) {
    __shared__ float sm[32][33];
    const int c0 = blockIdx.x * 32, k0 = blockIdx.y * 32;
    const int tx = threadIdx.x, ty = threadIdx.y;
#pragma unroll
    for (int rr = 0; rr < 4; rr++) {
        int k = k0 + ty + rr * 8;
        int c = c0 + tx;
        float v;
        if (c < 192) v = Wq[k * 192 + c];
        else if (c < 576) v = Wkv[k * 384 + (c - 192)];
        else if (c < 720) v = Wqp[k * 144 + (c - 576)];
        else v = Wkvp[k * 432 + (c - 720)];
        sm[ty + rr * 8][tx] = v;
    }
    __syncthreads();
#pragma unroll
    for (int rr = 0; rr < 4; rr++) {
        int c = c0 + ty + rr * 8;
        int k = k0 + tx;
        float v = sm[tx][ty + rr * 8];
        split_store(v, &g_Wth[(long)c * CS + k], &g_Wtl[(long)c * CS + k]);
    }
}

// transpose+convert Wout[2112][1024] -> g_WoT[1024][2112]
__global__ void WoutT_kernel(const float* __restrict__ Wout) {
    __shared__ float sm[32][33];
    const int n0 = blockIdx.x * 32, k0 = blockIdx.y * 32;
    const int tx = threadIdx.x, ty = threadIdx.y;
#pragma unroll
    for (int rr = 0; rr < 4; rr++)
        sm[ty + rr * 8][tx] = Wout[(long)(k0 + ty + rr * 8) * 1024 + n0 + tx];
    __syncthreads();
#pragma unroll
    for (int rr = 0; rr < 4; rr++) {
        int n = n0 + ty + rr * 8;
        int k = k0 + tx;
        float v = sm[tx][ty + rr * 8];
        split_store(v, &g_WoTh[(long)n * KCAT + k], &g_WoTl[(long)n * KCAT + k]);
    }
}

__global__ void packbias_kernel(const float* __restrict__ bq, const float* __restrict__ bkv,
                                const float* __restrict__ bqp, const float* __restrict__ bkvp) {
    int c = blockIdx.x * 256 + threadIdx.x;
    if (c < NPROJ) {
        float v;
        if (c < 192) v = bq[c];
        else if (c < 576) v = bkv[c - 192];
        else if (c < 720) v = bqp[c - 576];
        else v = bkvp[c - 720];
        g_bias[c] = v;
    }
}

// ---------------- fp32 SGEMM (kept for a @ vcat) ----------------------------
template <bool HAS_BIAS>
__global__ __launch_bounds__(256)
void gemm64(const float* __restrict__ A, const float* __restrict__ Bm,
            const float* __restrict__ bias, float* __restrict__ C,
            int M, int K, int Nw, long sA, long sB, long sC) {
    A += blockIdx.z * sA;
    Bm += blockIdx.z * sB;
    C += blockIdx.z * sC;

    __shared__ __align__(16) float As[2][16][68];
    __shared__ __align__(16) float Bs[2][16][64];

    const int tid = threadIdx.x;
    const int m0 = blockIdx.y * 64;
    const int n0 = blockIdx.x * 64;

    const int aRow = tid >> 2;
    const int aCol = (tid & 3) * 4;
    const int bRow = tid >> 4;
    const int bCol = (tid & 15) * 4;
    const int tm = tid >> 4;
    const int tn = tid & 15;

    const float* Ag = A + (long)(m0 + aRow) * K + aCol;
    const float* Bg = Bm + (long)bRow * Nw + n0 + bCol;
    const bool bPred = (n0 + bCol + 3) < Nw;

    float4 ra = *(const float4*)Ag;
    float4 rb = bPred ? *(const float4*)Bg : make_float4(0.f, 0.f, 0.f, 0.f);
    As[0][aCol + 0][aRow] = ra.x;
    As[0][aCol + 1][aRow] = ra.y;
    As[0][aCol + 2][aRow] = ra.z;
    As[0][aCol + 3][aRow] = ra.w;
    *(float4*)&Bs[0][bRow][bCol] = rb;
    __syncthreads();

    float acc[4][4];
#pragma unroll
    for (int r = 0; r < 4; r++)
#pragma unroll
        for (int c = 0; c < 4; c++) acc[r][c] = 0.f;

    const int T = K >> 4;
    for (int t = 0; t < T; t++) {
        const int cur = t & 1;
        if (t + 1 < T) {
            ra = *(const float4*)(Ag + (t + 1) * 16);
            rb = bPred ? *(const float4*)(Bg + (long)(t + 1) * 16 * Nw)
                       : make_float4(0.f, 0.f, 0.f, 0.f);
        }
#pragma unroll
        for (int kk = 0; kk < 16; kk++) {
            float4 a4 = *(const float4*)&As[cur][kk][tm * 4];
            float4 b4 = *(const float4*)&Bs[cur][kk][tn * 4];
            float ar[4] = {a4.x, a4.y, a4.z, a4.w};
            float br[4] = {b4.x, b4.y, b4.z, b4.w};
#pragma unroll
            for (int r = 0; r < 4; r++)
#pragma unroll
                for (int c = 0; c < 4; c++) acc[r][c] += ar[r] * br[c];
        }
        if (t + 1 < T) {
            const int nxt = cur ^ 1;
            As[nxt][aCol + 0][aRow] = ra.x;
            As[nxt][aCol + 1][aRow] = ra.y;
            As[nxt][aCol + 2][aRow] = ra.z;
            As[nxt][aCol + 3][aRow] = ra.w;
            *(float4*)&Bs[nxt][bRow][bCol] = rb;
            __syncthreads();
        }
    }

#pragma unroll
    for (int r = 0; r < 4; r++) {
        const int m = m0 + tm * 4 + r;
#pragma unroll
        for (int c = 0; c < 4; c++) {
            const int n = n0 + tn * 4 + c;
            if (n < Nw) {
                float v = acc[r][c];
                if (HAS_BIAS) v += bias[n];
                C[(long)m * Nw + n] = v;
            }
        }
    }
}

// ---------------- point transform + vcat fill -------------------------------
__global__ void pts_kernel(const float* __restrict__ rot, const float* __restrict__ trans) {
    const int i = blockIdx.x;
    const int t = threadIdx.x; // 384
    __shared__ float R[9], T[3];
    if (t < 9) R[t] = rot[i * 9 + t];
    if (t < 3) T[t] = trans[i * 3 + t];
    __syncthreads();

    const float* P = g_proj + (long)i * NPROJ;

    if (t < 48) {
        float l0 = P[576 + 0 * 48 + t];
        float l1 = P[576 + 1 * 48 + t];
        float l2 = P[576 + 2 * 48 + t];
#pragma unroll
        for (int ci = 0; ci < 3; ci++)
            g_qpts[i * 144 + 3 * t + ci] =
                R[ci * 3 + 0] * l0 + R[ci * 3 + 1] * l1 + R[ci * 3 + 2] * l2 + T[ci];
    } else if (t < 96) {
        int u = t - 48;
        int h = u >> 2, p = u & 3;
        int pidx = h * 12 + p;
        float l0 = P[720 + 0 * 144 + pidx];
        float l1 = P[720 + 1 * 144 + pidx];
        float l2 = P[720 + 2 * 144 + pidx];
#pragma unroll
        for (int ci = 0; ci < 3; ci++)
            g_kpts[i * 144 + 3 * u + ci] =
                R[ci * 3 + 0] * l0 + R[ci * 3 + 1] * l1 + R[ci * 3 + 2] * l2 + T[ci];
    } else if (t < 192) {
        int u = t - 96;
        int h = u >> 3, p = u & 7;
        int pidx = h * 12 + 4 + p;
        float l0 = P[720 + 0 * 144 + pidx];
        float l1 = P[720 + 1 * 144 + pidx];
        float l2 = P[720 + 2 * 144 + pidx];
#pragma unroll
        for (int ci = 0; ci < 3; ci++)
            g_vcat[((long)h * NN + i) * 40 + 16 + p * 3 + ci] =
                R[ci * 3 + 0] * l0 + R[ci * 3 + 1] * l1 + R[ci * 3 + 2] * l2 + T[ci];
    } else {
        int u = t - 192;
        int h = u >> 4, d = u & 15;
        g_vcat[((long)h * NN + i) * 40 + d] = P[192 + h * 32 + 16 + d];
    }
}

// ---------------- b = sqrt(1/3) * (z @ Wb + bb) -> g_a ----------------------
__global__ __launch_bounds__(256)
void bz_kernel(const float* __restrict__ z, const float* __restrict__ Wb,
               const float* __restrict__ bb) {
    __shared__ float4 ws4[Hh][32];
    __shared__ float bbs[Hh];
    __shared__ float zs[512][17];

    const int i = blockIdx.x;
    const int t = threadIdx.x;

    for (int idx = t; idx < Hh * 32; idx += 256) {
        int h = idx >> 5, c4 = idx & 31;
        ws4[h][c4] = make_float4(Wb[(c4 * 4 + 0) * Hh + h], Wb[(c4 * 4 + 1) * Hh + h],
                                 Wb[(c4 * 4 + 2) * Hh + h], Wb[(c4 * 4 + 3) * Hh + h]);
    }
    if (t < Hh) bbs[t] = bb[t];

    float acc0[Hh], acc1[Hh];
#pragma unroll
    for (int h = 0; h < Hh; h++) { acc0[h] = 0.f; acc1[h] = 0.f; }

    for (int c0 = 0; c0 < 128; c0 += 16) {
        __syncthreads();
        for (int idx = t; idx < 2048; idx += 256) {
            int r = idx >> 2, c4 = idx & 3;
            float4 v = *(const float4*)&z[((long)i * 512 + r) * 128 + c0 + c4 * 4];
            zs[r][c4 * 4 + 0] = v.x;
            zs[r][c4 * 4 + 1] = v.y;
            zs[r][c4 * 4 + 2] = v.z;
            zs[r][c4 * 4 + 3] = v.w;
        }
        __syncthreads();

        const int wb = c0 >> 2;
#pragma unroll
        for (int c4 = 0; c4 < 4; c4++) {
            float a0 = zs[t][c4 * 4 + 0], a1 = zs[t][c4 * 4 + 1];
            float a2 = zs[t][c4 * 4 + 2], a3 = zs[t][c4 * 4 + 3];
            float b0 = zs[t + 256][c4 * 4 + 0], b1 = zs[t + 256][c4 * 4 + 1];
            float b2 = zs[t + 256][c4 * 4 + 2], b3 = zs[t + 256][c4 * 4 + 3];
#pragma unroll
            for (int h = 0; h < Hh; h++) {
                float4 w = ws4[h][wb + c4];
                acc0[h] += a0 * w.x + a1 * w.y + a2 * w.z + a3 * w.w;
                acc1[h] += b0 * w.x + b1 * w.y + b2 * w.z + b3 * w.w;
            }
        }
    }

    const float k13 = 0.57735026918962576f;
#pragma unroll
    for (int h = 0; h < Hh; h++) {
        g_a[(((long)h << 9) + i) * 512 + t] = k13 * (acc0[h] + bbs[h]);
        g_a[(((long)h << 9) + i) * 512 + t + 256] = k13 * (acc1[h] + bbs[h]);
    }
}

// ---------------- fused logits + softmax ------------------------------------
__global__ __launch_bounds__(256)
void logits_softmax_kernel(const float* __restrict__ mask, const float* __restrict__ head_w) {
    const int h = blockIdx.y;
    const int i0 = blockIdx.x * 8;
    const int t = threadIdx.x;
    const int ti = t >> 5;
    const int lane = t & 31;

    __shared__ float ks[256][17];
    __shared__ float kps[256][13];
    __shared__ float mj[256];
    __shared__ float qs[8][16];
    __shared__ float qps[8][12];
    __shared__ float mi[8];

    if (t < 128) {
        int r = t >> 4, d = t & 15;
        qs[r][d] = g_proj[(long)(i0 + r) * NPROJ + h * 16 + d];
    } else if (t < 224) {
        int u = t - 128;
        int r = u / 12, d = u % 12;
        qps[r][d] = g_qpts[(i0 + r) * 144 + h * 12 + d];
    } else if (t < 232) {
        mi[t - 224] = mask[i0 + (t - 224)];
    }

    float x = head_w[h];
    float sp = (x > 20.f) ? x : log1pf(expf(x));
    const float hw = sp * 0.13608276348795434f;
    const float kqk = 0.14433756729740643f;

    float v[16];
    const long rowBase = (((long)h << 9) + i0 + ti) * 512;

    for (int jc = 0; jc < 2; jc++) {
        const int jbase = jc * 256;
        __syncthreads();
        for (int idx = t; idx < 256 * 16; idx += 256) {
            int r = idx >> 4, d = idx & 15;
            ks[r][d] = g_proj[(long)(jbase + r) * NPROJ + 192 + h * 32 + d];
        }
        for (int idx = t; idx < 256 * 12; idx += 256) {
            int r = idx / 12, d = idx % 12;
            kps[r][d] = g_kpts[(jbase + r) * 144 + h * 12 + d];
        }
        if (t < 256) mj[t] = mask[jbase + t];
        __syncthreads();

#pragma unroll
        for (int q = 0; q < 8; q++) {
            const int r = lane + q * 32;
            float dot = 0.f;
#pragma unroll
            for (int d = 0; d < 16; d++) dot += qs[ti][d] * ks[r][d];
            float pt = 0.f;
#pragma unroll
            for (int pc = 0; pc < 12; pc++) {
                float df = qps[ti][pc] - kps[r][pc];
                pt += df * df;
            }
            float b = g_a[rowBase + jbase + r];
            v[jc * 8 + q] = dot * kqk + b - 0.5f * hw * pt
                          + 100000.0f * (mi[ti] * mj[r] - 1.0f);
        }
    }

    float m = v[0];
#pragma unroll
    for (int q = 1; q < 16; q++) m = fmaxf(m, v[q]);
#pragma unroll
    for (int o = 16; o; o >>= 1) m = fmaxf(m, __shfl_xor_sync(0xffffffffu, m, o));

    float s = 0.f;
#pragma unroll
    for (int q = 0; q < 16; q++) { v[q] = expf(v[q] - m); s += v[q]; }
#pragma unroll
    for (int o = 16; o; o >>= 1) s += __shfl_xor_sync(0xffffffffu, s, o);
    const float inv = 1.f / s;

#pragma unroll
    for (int q = 0; q < 16; q++) {
        int j = (q >> 3) * 256 + (q & 7) * 32 + lane;
        g_a[rowBase + j] = v[q] * inv;
    }
}

// ---------------- o_pair -> cat (bf16 hi/lo direct) -------------------------
__global__ __launch_bounds__(256)
void opair_kernel(const float* __restrict__ z) {
    const int i = blockIdx.x;
    __shared__ __align__(16) float sa[12][512];
    __shared__ __align__(16) float zs[32][128];
    const int t = threadIdx.x; // 256

    for (int idx = t; idx < 12 * 512; idx += 256) {
        int h = idx >> 9, j = idx & 511;
        sa[h][j] = g_a[(((long)h << 9) + i) * 512 + j];
    }

    const int c = t & 127;
    const int hh = t >> 7;
    float acc[6] = {0.f, 0.f, 0.f, 0.f, 0.f, 0.f};

    for (int j0 = 0; j0 < 512; j0 += 32) {
        __syncthreads();
        for (int idx = t; idx < 32 * 128; idx += 256) {
            int r = idx >> 7, cc = idx & 127;
            zs[r][cc] = z[(((long)i << 9) + j0 + r) * 128 + cc];
        }
        __syncthreads();
#pragma unroll
        for (int r4 = 0; r4 < 8; r4++) {
            float z0 = zs[r4 * 4 + 0][c];
            float z1 = zs[r4 * 4 + 1][c];
            float z2 = zs[r4 * 4 + 2][c];
            float z3 = zs[r4 * 4 + 3][c];
#pragma unroll
            for (int q = 0; q < 6; q++) {
                float4 s4 = *(const float4*)&sa[hh * 6 + q][j0 + r4 * 4];
                acc[q] += s4.x * z0 + s4.y * z1 + s4.z * z2 + s4.w * z3;
            }
        }
    }
#pragma unroll
    for (int q = 0; q < 6; q++) {
        long idx = (long)i * KCAT + 576 + (hh * 6 + q) * 128 + c;
        split_store(acc[q], &g_cath[idx], &g_catl[idx]);
    }
}

// ---------------- assemble: o copy + inverse-frame o_pt + norms (bf16) ------
__global__ void assemble_kernel(const float* __restrict__ rot, const float* __restrict__ trans) {
    const int i = blockIdx.x;
    const int t = threadIdx.x; // 192
    __shared__ float R[9], T[3];
    if (t < 9) R[t] = rot[i * 9 + t];
    if (t < 3) T[t] = trans[i * 3 + t];
    __syncthreads();

    {
        int h = t >> 4, d = t & 15;
        long idx = (long)i * KCAT + t;
        split_store(g_o1[((long)h * NN + i) * 40 + d], &g_cath[idx], &g_catl[idx]);
    }
    if (t < 96) {
        int h = t >> 3, p = t & 7;
        const float* src = &g_o1[((long)h * NN + i) * 40 + 16 + p * 3];
        float w0 = src[0] - T[0];
        float w1 = src[1] - T[1];
        float w2 = src[2] - T[2];
        float l0 = R[0] * w0 + R[3] * w1 + R[6] * w2;
        float l1 = R[1] * w0 + R[4] * w1 + R[7] * w2;
        float l2 = R[2] * w0 + R[5] * w1 + R[8] * w2;
        long b = (long)i * KCAT;
        split_store(l0, &g_cath[b + 192 + t], &g_catl[b + 192 + t]);
        split_store(l1, &g_cath[b + 288 + t], &g_catl[b + 288 + t]);
        split_store(l2, &g_cath[b + 384 + t], &g_catl[b + 384 + t]);
        float nrm = sqrtf(l0 * l0 + l1 * l1 + l2 * l2 + 1e-8f);
        split_store(nrm, &g_cath[b + 480 + t], &g_catl[b + 480 + t]);
    }
}

// ---------------- stream/event state (lazy init, host-side only) ------------
static cudaStream_t g_s1 = nullptr, g_s2 = nullptr;
static cudaEvent_t g_evRoot, g_evBz, g_evWo, g_evLS, g_evOp;

// ---------------- launch ----------------------------------------------------
extern "C" void kernel_launch(void* const* d_in, const int* in_sizes, int n_in,
                              void* d_out, int out_size) {
    const float* s     = (const float*)d_in[0];
    const float* z     = (const float*)d_in[1];
    const float* rot   = (const float*)d_in[2];
    const float* trans = (const float*)d_in[3];
    const float* mask  = (const float*)d_in[4];
    const float* Wq    = (const float*)d_in[5];
    const float* bq    = (const float*)d_in[6];
    const float* Wkv   = (const float*)d_in[7];
    const float* bkv   = (const float*)d_in[8];
    const float* Wqp   = (const float*)d_in[9];
    const float* bqp   = (const float*)d_in[10];
    const float* Wkvp  = (const float*)d_in[11];
    const float* bkvp  = (const float*)d_in[12];
    const float* Wb    = (const float*)d_in[13];
    const float* bb    = (const float*)d_in[14];
    const float* head_w= (const float*)d_in[15];
    const float* Wout  = (const float*)d_in[16];
    const float* bout  = (const float*)d_in[17];
    float* out = (float*)d_out;

    if (!g_s1) {
        cudaStreamCreateWithFlags(&g_s1, cudaStreamNonBlocking);
        cudaStreamCreateWithFlags(&g_s2, cudaStreamNonBlocking);
        cudaEventCreateWithFlags(&g_evRoot, cudaEventDisableTiming);
        cudaEventCreateWithFlags(&g_evBz, cudaEventDisableTiming);
        cudaEventCreateWithFlags(&g_evWo, cudaEventDisableTiming);
        cudaEventCreateWithFlags(&g_evLS, cudaEventDisableTiming);
        cudaEventCreateWithFlags(&g_evOp, cudaEventDisableTiming);
    }

    float *pBias, *pProj, *pA, *pVcat, *pO1;
    __nv_bfloat16 *pSh, *pSl, *pWth, *pWtl, *pWoTh, *pWoTl, *pCath, *pCatl;
    cudaGetSymbolAddress((void**)&pBias, g_bias);
    cudaGetSymbolAddress((void**)&pProj, g_proj);
    cudaGetSymbolAddress((void**)&pA, g_a);
    cudaGetSymbolAddress((void**)&pVcat, g_vcat);
    cudaGetSymbolAddress((void**)&pO1, g_o1);
    cudaGetSymbolAddress((void**)&pSh, g_sh);
    cudaGetSymbolAddress((void**)&pSl, g_sl);
    cudaGetSymbolAddress((void**)&pWth, g_Wth);
    cudaGetSymbolAddress((void**)&pWtl, g_Wtl);
    cudaGetSymbolAddress((void**)&pWoTh, g_WoTh);
    cudaGetSymbolAddress((void**)&pWoTl, g_WoTl);
    cudaGetSymbolAddress((void**)&pCath, g_cath);
    cudaGetSymbolAddress((void**)&pCatl, g_catl);

    // fork side streams off the capture (root) stream
    cudaEventRecord(g_evRoot, 0);
    cudaStreamWaitEvent(g_s1, g_evRoot, 0);
    cudaStreamWaitEvent(g_s2, g_evRoot, 0);

    // s1: z-bound bz (independent of projection chain), then WoutT
    bz_kernel<<<512, 256, 0, g_s1>>>(z, Wb, bb);
    cudaEventRecord(g_evBz, g_s1);
    WoutT_kernel<<<dim3(1024 / 32, KCAT / 32), dim3(32, 8), 0, g_s1>>>(Wout);
    cudaEventRecord(g_evWo, g_s1);

    // main chain: operand prep -> proj -> pts
    conv_hl_kernel<<<(NN * CS + 255) / 256, 256>>>(s, pSh, pSl, NN * CS);
    packWT_kernel<<<dim3(NPROJ / 32, CS / 32), dim3(32, 8)>>>(Wq, Wkv, Wqp, Wkvp);
    packbias_kernel<<<(NPROJ + 255) / 256, 256>>>(bq, bkv, bqp, bkvp);
    hgemm<true><<<dim3(NPROJ / 64, NN / 64), 256>>>(pSh, pSl, pWth, pWtl, pBias, pProj,
                                                    NN, CS, NPROJ);
    pts_kernel<<<512, 384>>>(rot, trans);

    // logits needs bz output
    cudaStreamWaitEvent(0, g_evBz, 0);
    logits_softmax_kernel<<<dim3(64, 12), 256>>>(mask, head_w);
    cudaEventRecord(g_evLS, 0);

    // s2: opair (z-bound) concurrent with attn GEMM + assemble
    cudaStreamWaitEvent(g_s2, g_evLS, 0);
    opair_kernel<<<512, 256, 0, g_s2>>>(z);
    cudaEventRecord(g_evOp, g_s2);

    // main: attention output + assemble
    gemm64<false><<<dim3(1, 8, 12), 256>>>(pA, pVcat, nullptr, pO1, 512, 512, 40,
                                           (long)512 * 512, (long)512 * 40, (long)512 * 40);
    assemble_kernel<<<512, 192>>>(rot, trans);

    // join everything, then final GEMM
    cudaStreamWaitEvent(0, g_evOp, 0);
    cudaStreamWaitEvent(0, g_evWo, 0);
    hgemm<true><<<dim3(1024 / 64, NN / 64), 256>>>(pCath, pCatl, pWoTh, pWoTl, bout, out,
                                                   NN, KCAT, 1024);
}

// round 12
// speedup vs baseline: 2.5081x; 1.2843x over previous
#include <cuda_runtime.h>
#include <cuda_bf16.h>
#include <math.h>
#include <stdint.h>

#define NN 512
#define CS 1024
#define CZd 128
#define Hh 12
#define HDd 16
#define PQp 4
#define PVp 8
#define NPROJ 1152   // 192 q | 384 kv | 144 qp | 432 kvp
#define KCAT 2112

// ---------------- scratch (device globals; no allocation allowed) ----------
__device__ __align__(16) float g_bias[NPROJ];
__device__ __align__(16) float g_proj[NN * NPROJ];
__device__ __align__(16) float g_qpts[NN * Hh * PQp * 3];
__device__ __align__(16) float g_kpts[NN * Hh * PQp * 3];
__device__ __align__(16) float g_vcat[Hh * NN * 40];
__device__ __align__(16) float g_a[Hh * NN * NN];
__device__ __align__(16) float g_o1[Hh * NN * 40];

// bf16 split operands for tensor-core GEMMs
__device__ __align__(16) __nv_bfloat16 g_sh[NN * CS];
__device__ __align__(16) __nv_bfloat16 g_sl[NN * CS];
__device__ __align__(16) __nv_bfloat16 g_Wth[NPROJ * CS];   // W^T [n][k] K-major
__device__ __align__(16) __nv_bfloat16 g_Wtl[NPROJ * CS];
__device__ __align__(16) __nv_bfloat16 g_WoTh[1024 * KCAT]; // Wout^T [n][k]
__device__ __align__(16) __nv_bfloat16 g_WoTl[1024 * KCAT];
__device__ __align__(16) __nv_bfloat16 g_cath[NN * KCAT];
__device__ __align__(16) __nv_bfloat16 g_catl[NN * KCAT];

// ---------------- warp-level bf16 MMA + ldmatrix (baseline PTX) -------------
__device__ __forceinline__ void mma16816(float* c, const uint32_t* a, const uint32_t* b) {
    asm volatile(
        "mma.sync.aligned.m16n8k16.row.col.f32.bf16.bf16.f32 "
        "{%0,%1,%2,%3}, {%4,%5,%6,%7}, {%8,%9}, {%0,%1,%2,%3};"
        : "+f"(c[0]), "+f"(c[1]), "+f"(c[2]), "+f"(c[3])
        : "r"(a[0]), "r"(a[1]), "r"(a[2]), "r"(a[3]), "r"(b[0]), "r"(b[1]));
}
__device__ __forceinline__ void ldmx4(uint32_t* r, uint32_t addr) {
    asm volatile("ldmatrix.sync.aligned.m8n8.x4.shared.b16 {%0,%1,%2,%3}, [%4];"
                 : "=r"(r[0]), "=r"(r[1]), "=r"(r[2]), "=r"(r[3]) : "r"(addr));
}
__device__ __forceinline__ void ldmx2(uint32_t* r, uint32_t addr) {
    asm volatile("ldmatrix.sync.aligned.m8n8.x2.shared.b16 {%0,%1}, [%2];"
                 : "=r"(r[0]), "=r"(r[1]) : "r"(addr));
}
__device__ __forceinline__ uint32_t smem_u32(const void* p) {
    uint32_t a;
    asm("{ .reg .u64 t; cvta.to.shared.u64 t, %1; cvt.u32.u64 %0, t; }" : "=r"(a) : "l"(p));
    return a;
}
__device__ __forceinline__ void split_store(float v, __nv_bfloat16* dh, __nv_bfloat16* dl) {
    __nv_bfloat16 hi = __float2bfloat16(v);
    *dh = hi;
    *dl = __float2bfloat16(v - __bfloat162float(hi));
}

// ---------------- hgemm v2: C = A @ B^T, split-bf16, HMMA -------------------
// A: [M][K] bf16 hi/lo (K contiguous). B: [Nw][K] bf16 hi/lo (K contiguous).
// C fp32 [M][Nw] (+bias). M%64==0, Nw%64==0, K%32==0.
// grid (Nw/64, M/64), block 256 (8 warps: 4 m-bands x 2 n-bands).
// LDG.128 global loads, 2-stage smem double-buffer, ldmatrix fragments.
template <bool HAS_BIAS>
__global__ __launch_bounds__(256)
void hgemm(const __nv_bfloat16* __restrict__ Ah_, const __nv_bfloat16* __restrict__ Al_,
           const __nv_bfloat16* __restrict__ Bh_, const __nv_bfloat16* __restrict__ Bl_,
           const float* __restrict__ bias, float* __restrict__ C,
           int M, int K, int Nw) {
    // [stage][array(Ah,Al,Bh,Bl)][64 rows * 20 words] (16 data words + 4 pad)
    __shared__ __align__(16) uint32_t sm[2][4][64 * 20];

    const int t = threadIdx.x;
    const int wid = t >> 5, lane = t & 31;
    const int wm = wid >> 1, wn = wid & 1;
    const int lr = lane >> 2, lc = lane & 3;
    const int m0 = blockIdx.y * 64, n0 = blockIdx.x * 64;
    const int K2 = K >> 1;                 // u32 words per row
    const int NC = K2 >> 4;                // 16-word chunks

    const uint32_t* Ah32 = (const uint32_t*)Ah_;
    const uint32_t* Al32 = (const uint32_t*)Al_;
    const uint32_t* Bh32 = (const uint32_t*)Bh_;
    const uint32_t* Bl32 = (const uint32_t*)Bl_;

    // global: thread t loads row grow, words gw..gw+3 of each array per chunk
    const int grow = t >> 2, gw = (t & 3) * 4;
    const long aBase = (long)(m0 + grow) * K2 + gw;
    const long bBase = (long)(n0 + grow) * K2 + gw;
    const int sIdx = grow * 20 + gw;       // smem word index for stores

    // ldmatrix per-lane addresses (word offsets within one array tile)
    const uint32_t smb = smem_u32(sm);
    const int aRowOff = (16 * wm + (lane & 15)) * 20 + ((lane >> 4) << 2);
    const int bRowOff0 = (32 * wn + (lane & 7)) * 20 + (((lane >> 3) & 1) << 2);

    float acc[4][4];
#pragma unroll
    for (int j = 0; j < 4; j++)
#pragma unroll
        for (int r = 0; r < 4; r++) acc[j][r] = 0.f;

    // prologue: chunk 0 -> stage 0
    uint4 rAh = *(const uint4*)(Ah32 + aBase);
    uint4 rAl = *(const uint4*)(Al32 + aBase);
    uint4 rBh = *(const uint4*)(Bh32 + bBase);
    uint4 rBl = *(const uint4*)(Bl32 + bBase);
    *(uint4*)&sm[0][0][sIdx] = rAh;
    *(uint4*)&sm[0][1][sIdx] = rAl;
    *(uint4*)&sm[0][2][sIdx] = rBh;
    *(uint4*)&sm[0][3][sIdx] = rBl;
    __syncthreads();

    for (int c = 0; c < NC; c++) {
        const int cur = c & 1;
        if (c + 1 < NC) {
            const long off = (long)(c + 1) * 16;
            rAh = *(const uint4*)(Ah32 + aBase + off);
            rAl = *(const uint4*)(Al32 + aBase + off);
            rBh = *(const uint4*)(Bh32 + bBase + off);
            rBl = *(const uint4*)(Bl32 + bBase + off);
        }

        const uint32_t baseAh = smb + ((cur * 4 + 0) * 1280) * 4;
        const uint32_t baseAl = smb + ((cur * 4 + 1) * 1280) * 4;
        const uint32_t baseBh = smb + ((cur * 4 + 2) * 1280) * 4;
        const uint32_t baseBl = smb + ((cur * 4 + 3) * 1280) * 4;

#pragma unroll
        for (int ks = 0; ks < 2; ks++) {
            const int kb = ks * 8;
            uint32_t ah[4], al[4];
            ldmx4(ah, baseAh + (aRowOff + kb) * 4);
            ldmx4(al, baseAl + (aRowOff + kb) * 4);
#pragma unroll
            for (int j = 0; j < 4; j++) {
                uint32_t bh[2], bl[2];
                const uint32_t bo = (bRowOff0 + j * 8 * 20 + kb) * 4;
                ldmx2(bh, baseBh + bo);
                ldmx2(bl, baseBl + bo);
                mma16816(acc[j], ah, bh);
                mma16816(acc[j], ah, bl);
                mma16816(acc[j], al, bh);
            }
        }

        if (c + 1 < NC) {
            const int nxt = cur ^ 1;
            *(uint4*)&sm[nxt][0][sIdx] = rAh;
            *(uint4*)&sm[nxt][1][sIdx] = rAl;
            *(uint4*)&sm[nxt][2][sIdx] = rBh;
            *(uint4*)&sm[nxt][3][sIdx] = rBl;
            __syncthreads();
        }
    }

    const int mrow = m0 + 16 * wm + lr;
#pragma unroll
    for (int j = 0; j < 4; j++) {
        const int n = n0 + 32 * wn + 8 * j + lc * 2;
        float b0 = HAS_BIAS ? bias[n] : 0.f;
        float b1 = HAS_BIAS ? bias[n + 1] : 0.f;
        C[(long)mrow * Nw + n] = acc[j][0] + b0;
        C[(long)mrow * Nw + n + 1] = acc[j][1] + b1;
        C[(long)(mrow + 8) * Nw + n] = acc[j][2] + b0;
        C[(long)(mrow + 8) * Nw + n + 1] = acc[j][3] + b1;
    }
}

// ---------------- conversions / transposes ----------------------------------
__global__ void conv_hl_kernel(const float* __restrict__ src, __nv_bfloat16* __restrict__ dh,
                               __nv_bfloat16* __restrict__ dl, int n) {
    int idx = blockIdx.x * 256 + threadIdx.x;
    if (idx < n) split_store(src[idx], dh + idx, dl + idx);
}

// pack+transpose+convert proj weights: virtual W[k=1024][c=1152] -> g_Wt[c][k]
__global__ void packWT_kernel(const float* __restrict__ Wq, const float* __restrict__ Wkv,
                              const float* __restrict__ Wqp, const float* __restrict__ Wkvp) {
    __shared__ float sm[32][33];
    const int c0 = blockIdx.x * 32, k0 = blockIdx.y * 32;
    const int tx = threadIdx.x, ty = threadIdx.y;
#pragma unroll
    for (int rr = 0; rr < 4; rr++) {
        int k = k0 + ty + rr * 8;
        int c = c0 + tx;
        float v;
        if (c < 192) v = Wq[k * 192 + c];
        else if (c < 576) v = Wkv[k * 384 + (c - 192)];
        else if (c < 720) v = Wqp[k * 144 + (c - 576)];
        else v = Wkvp[k * 432 + (c - 720)];
        sm[ty + rr * 8][tx] = v;
    }
    __syncthreads();
#pragma unroll
    for (int rr = 0; rr < 4; rr++) {
        int c = c0 + ty + rr * 8;
        int k = k0 + tx;
        float v = sm[tx][ty + rr * 8];
        split_store(v, &g_Wth[(long)c * CS + k], &g_Wtl[(long)c * CS + k]);
    }
}

// transpose+convert Wout[2112][1024] -> g_WoT[1024][2112]
__global__ void WoutT_kernel(const float* __restrict__ Wout) {
    __shared__ float sm[32][33];
    const int n0 = blockIdx.x * 32, k0 = blockIdx.y * 32;
    const int tx = threadIdx.x, ty = threadIdx.y;
#pragma unroll
    for (int rr = 0; rr < 4; rr++)
        sm[ty + rr * 8][tx] = Wout[(long)(k0 + ty + rr * 8) * 1024 + n0 + tx];
    __syncthreads();
#pragma unroll
    for (int rr = 0; rr < 4; rr++) {
        int n = n0 + ty + rr * 8;
        int k = k0 + tx;
        float v = sm[tx][ty + rr * 8];
        split_store(v, &g_WoTh[(long)n * KCAT + k], &g_WoTl[(long)n * KCAT + k]);
    }
}

__global__ void packbias_kernel(const float* __restrict__ bq, const float* __restrict__ bkv,
                                const float* __restrict__ bqp, const float* __restrict__ bkvp) {
    int c = blockIdx.x * 256 + threadIdx.x;
    if (c < NPROJ) {
        float v;
        if (c < 192) v = bq[c];
        else if (c < 576) v = bkv[c - 192];
        else if (c < 720) v = bqp[c - 576];
        else v = bkvp[c - 720];
        g_bias[c] = v;
    }
}

// ---------------- fp32 SGEMM (kept for a @ vcat) ----------------------------
template <bool HAS_BIAS>
__global__ __launch_bounds__(256)
void gemm64(const float* __restrict__ A, const float* __restrict__ Bm,
            const float* __restrict__ bias, float* __restrict__ C,
            int M, int K, int Nw, long sA, long sB, long sC) {
    A += blockIdx.z * sA;
    Bm += blockIdx.z * sB;
    C += blockIdx.z * sC;

    __shared__ __align__(16) float As[2][16][68];
    __shared__ __align__(16) float Bs[2][16][64];

    const int tid = threadIdx.x;
    const int m0 = blockIdx.y * 64;
    const int n0 = blockIdx.x * 64;

    const int aRow = tid >> 2;
    const int aCol = (tid & 3) * 4;
    const int bRow = tid >> 4;
    const int bCol = (tid & 15) * 4;
    const int tm = tid >> 4;
    const int tn = tid & 15;

    const float* Ag = A + (long)(m0 + aRow) * K + aCol;
    const float* Bg = Bm + (long)bRow * Nw + n0 + bCol;
    const bool bPred = (n0 + bCol + 3) < Nw;

    float4 ra = *(const float4*)Ag;
    float4 rb = bPred ? *(const float4*)Bg : make_float4(0.f, 0.f, 0.f, 0.f);
    As[0][aCol + 0][aRow] = ra.x;
    As[0][aCol + 1][aRow] = ra.y;
    As[0][aCol + 2][aRow] = ra.z;
    As[0][aCol + 3][aRow] = ra.w;
    *(float4*)&Bs[0][bRow][bCol] = rb;
    __syncthreads();

    float acc[4][4];
#pragma unroll
    for (int r = 0; r < 4; r++)
#pragma unroll
        for (int c = 0; c < 4; c++) acc[r][c] = 0.f;

    const int T = K >> 4;
    for (int t = 0; t < T; t++) {
        const int cur = t & 1;
        if (t + 1 < T) {
            ra = *(const float4*)(Ag + (t + 1) * 16);
            rb = bPred ? *(const float4*)(Bg + (long)(t + 1) * 16 * Nw)
                       : make_float4(0.f, 0.f, 0.f, 0.f);
        }
#pragma unroll
        for (int kk = 0; kk < 16; kk++) {
            float4 a4 = *(const float4*)&As[cur][kk][tm * 4];
            float4 b4 = *(const float4*)&Bs[cur][kk][tn * 4];
            float ar[4] = {a4.x, a4.y, a4.z, a4.w};
            float br[4] = {b4.x, b4.y, b4.z, b4.w};
#pragma unroll
            for (int r = 0; r < 4; r++)
#pragma unroll
                for (int c = 0; c < 4; c++) acc[r][c] += ar[r] * br[c];
        }
        if (t + 1 < T) {
            const int nxt = cur ^ 1;
            As[nxt][aCol + 0][aRow] = ra.x;
            As[nxt][aCol + 1][aRow] = ra.y;
            As[nxt][aCol + 2][aRow] = ra.z;
            As[nxt][aCol + 3][aRow] = ra.w;
            *(float4*)&Bs[nxt][bRow][bCol] = rb;
            __syncthreads();
        }
    }

#pragma unroll
    for (int r = 0; r < 4; r++) {
        const int m = m0 + tm * 4 + r;
#pragma unroll
        for (int c = 0; c < 4; c++) {
            const int n = n0 + tn * 4 + c;
            if (n < Nw) {
                float v = acc[r][c];
                if (HAS_BIAS) v += bias[n];
                C[(long)m * Nw + n] = v;
            }
        }
    }
}

// ---------------- point transform + vcat fill -------------------------------
__global__ void pts_kernel(const float* __restrict__ rot, const float* __restrict__ trans) {
    const int i = blockIdx.x;
    const int t = threadIdx.x; // 384
    __shared__ float R[9], T[3];
    if (t < 9) R[t] = rot[i * 9 + t];
    if (t < 3) T[t] = trans[i * 3 + t];
    __syncthreads();

    const float* P = g_proj + (long)i * NPROJ;

    if (t < 48) {
        float l0 = P[576 + 0 * 48 + t];
        float l1 = P[576 + 1 * 48 + t];
        float l2 = P[576 + 2 * 48 + t];
#pragma unroll
        for (int ci = 0; ci < 3; ci++)
            g_qpts[i * 144 + 3 * t + ci] =
                R[ci * 3 + 0] * l0 + R[ci * 3 + 1] * l1 + R[ci * 3 + 2] * l2 + T[ci];
    } else if (t < 96) {
        int u = t - 48;
        int h = u >> 2, p = u & 3;
        int pidx = h * 12 + p;
        float l0 = P[720 + 0 * 144 + pidx];
        float l1 = P[720 + 1 * 144 + pidx];
        float l2 = P[720 + 2 * 144 + pidx];
#pragma unroll
        for (int ci = 0; ci < 3; ci++)
            g_kpts[i * 144 + 3 * u + ci] =
                R[ci * 3 + 0] * l0 + R[ci * 3 + 1] * l1 + R[ci * 3 + 2] * l2 + T[ci];
    } else if (t < 192) {
        int u = t - 96;
        int h = u >> 3, p = u & 7;
        int pidx = h * 12 + 4 + p;
        float l0 = P[720 + 0 * 144 + pidx];
        float l1 = P[720 + 1 * 144 + pidx];
        float l2 = P[720 + 2 * 144 + pidx];
#pragma unroll
        for (int ci = 0; ci < 3; ci++)
            g_vcat[((long)h * NN + i) * 40 + 16 + p * 3 + ci] =
                R[ci * 3 + 0] * l0 + R[ci * 3 + 1] * l1 + R[ci * 3 + 2] * l2 + T[ci];
    } else {
        int u = t - 192;
        int h = u >> 4, d = u & 15;
        g_vcat[((long)h * NN + i) * 40 + d] = P[192 + h * 32 + 16 + d];
    }
}

// ---------------- b = sqrt(1/3) * (z @ Wb + bb) -> g_a ----------------------
__global__ __launch_bounds__(256)
void bz_kernel(const float* __restrict__ z, const float* __restrict__ Wb,
               const float* __restrict__ bb) {
    __shared__ float4 ws4[Hh][32];
    __shared__ float bbs[Hh];
    __shared__ float zs[512][17];

    const int i = blockIdx.x;
    const int t = threadIdx.x;

    for (int idx = t; idx < Hh * 32; idx += 256) {
        int h = idx >> 5, c4 = idx & 31;
        ws4[h][c4] = make_float4(Wb[(c4 * 4 + 0) * Hh + h], Wb[(c4 * 4 + 1) * Hh + h],
                                 Wb[(c4 * 4 + 2) * Hh + h], Wb[(c4 * 4 + 3) * Hh + h]);
    }
    if (t < Hh) bbs[t] = bb[t];

    float acc0[Hh], acc1[Hh];
#pragma unroll
    for (int h = 0; h < Hh; h++) { acc0[h] = 0.f; acc1[h] = 0.f; }

    for (int c0 = 0; c0 < 128; c0 += 16) {
        __syncthreads();
        for (int idx = t; idx < 2048; idx += 256) {
            int r = idx >> 2, c4 = idx & 3;
            float4 v = *(const float4*)&z[((long)i * 512 + r) * 128 + c0 + c4 * 4];
            zs[r][c4 * 4 + 0] = v.x;
            zs[r][c4 * 4 + 1] = v.y;
            zs[r][c4 * 4 + 2] = v.z;
            zs[r][c4 * 4 + 3] = v.w;
        }
        __syncthreads();

        const int wb = c0 >> 2;
#pragma unroll
        for (int c4 = 0; c4 < 4; c4++) {
            float a0 = zs[t][c4 * 4 + 0], a1 = zs[t][c4 * 4 + 1];
            float a2 = zs[t][c4 * 4 + 2], a3 = zs[t][c4 * 4 + 3];
            float b0 = zs[t + 256][c4 * 4 + 0], b1 = zs[t + 256][c4 * 4 + 1];
            float b2 = zs[t + 256][c4 * 4 + 2], b3 = zs[t + 256][c4 * 4 + 3];
#pragma unroll
            for (int h = 0; h < Hh; h++) {
                float4 w = ws4[h][wb + c4];
                acc0[h] += a0 * w.x + a1 * w.y + a2 * w.z + a3 * w.w;
                acc1[h] += b0 * w.x + b1 * w.y + b2 * w.z + b3 * w.w;
            }
        }
    }

    const float k13 = 0.57735026918962576f;
#pragma unroll
    for (int h = 0; h < Hh; h++) {
        g_a[(((long)h << 9) + i) * 512 + t] = k13 * (acc0[h] + bbs[h]);
        g_a[(((long)h << 9) + i) * 512 + t + 256] = k13 * (acc1[h] + bbs[h]);
    }
}

// ---------------- fused logits + softmax ------------------------------------
__global__ __launch_bounds__(256)
void logits_softmax_kernel(const float* __restrict__ mask, const float* __restrict__ head_w) {
    const int h = blockIdx.y;
    const int i0 = blockIdx.x * 8;
    const int t = threadIdx.x;
    const int ti = t >> 5;
    const int lane = t & 31;

    __shared__ float ks[256][17];
    __shared__ float kps[256][13];
    __shared__ float mj[256];
    __shared__ float qs[8][16];
    __shared__ float qps[8][12];
    __shared__ float mi[8];

    if (t < 128) {
        int r = t >> 4, d = t & 15;
        qs[r][d] = g_proj[(long)(i0 + r) * NPROJ + h * 16 + d];
    } else if (t < 224) {
        int u = t - 128;
        int r = u / 12, d = u % 12;
        qps[r][d] = g_qpts[(i0 + r) * 144 + h * 12 + d];
    } else if (t < 232) {
        mi[t - 224] = mask[i0 + (t - 224)];
    }

    float x = head_w[h];
    float sp = (x > 20.f) ? x : log1pf(expf(x));
    const float hw = sp * 0.13608276348795434f;
    const float kqk = 0.14433756729740643f;

    float v[16];
    const long rowBase = (((long)h << 9) + i0 + ti) * 512;

    for (int jc = 0; jc < 2; jc++) {
        const int jbase = jc * 256;
        __syncthreads();
        for (int idx = t; idx < 256 * 16; idx += 256) {
            int r = idx >> 4, d = idx & 15;
            ks[r][d] = g_proj[(long)(jbase + r) * NPROJ + 192 + h * 32 + d];
        }
        for (int idx = t; idx < 256 * 12; idx += 256) {
            int r = idx / 12, d = idx % 12;
            kps[r][d] = g_kpts[(jbase + r) * 144 + h * 12 + d];
        }
        if (t < 256) mj[t] = mask[jbase + t];
        __syncthreads();

#pragma unroll
        for (int q = 0; q < 8; q++) {
            const int r = lane + q * 32;
            float dot = 0.f;
#pragma unroll
            for (int d = 0; d < 16; d++) dot += qs[ti][d] * ks[r][d];
            float pt = 0.f;
#pragma unroll
            for (int pc = 0; pc < 12; pc++) {
                float df = qps[ti][pc] - kps[r][pc];
                pt += df * df;
            }
            float b = g_a[rowBase + jbase + r];
            v[jc * 8 + q] = dot * kqk + b - 0.5f * hw * pt
                          + 100000.0f * (mi[ti] * mj[r] - 1.0f);
        }
    }

    float m = v[0];
#pragma unroll
    for (int q = 1; q < 16; q++) m = fmaxf(m, v[q]);
#pragma unroll
    for (int o = 16; o; o >>= 1) m = fmaxf(m, __shfl_xor_sync(0xffffffffu, m, o));

    float s = 0.f;
#pragma unroll
    for (int q = 0; q < 16; q++) { v[q] = expf(v[q] - m); s += v[q]; }
#pragma unroll
    for (int o = 16; o; o >>= 1) s += __shfl_xor_sync(0xffffffffu, s, o);
    const float inv = 1.f / s;

#pragma unroll
    for (int q = 0; q < 16; q++) {
        int j = (q >> 3) * 256 + (q & 7) * 32 + lane;
        g_a[rowBase + j] = v[q] * inv;
    }
}

// ---------------- o_pair -> cat (bf16 hi/lo direct) -------------------------
__global__ __launch_bounds__(256)
void opair_kernel(const float* __restrict__ z) {
    const int i = blockIdx.x;
    __shared__ __align__(16) float sa[12][512];
    __shared__ __align__(16) float zs[32][128];
    const int t = threadIdx.x; // 256

    for (int idx = t; idx < 12 * 128; idx += 256) {
        int h = idx / 128, j4 = idx % 128;
        ((float4*)&sa[h][0])[j4] = ((const float4*)&g_a[(((long)h << 9) + i) * 512])[j4];
    }

    const int c = t & 127;
    const int hh = t >> 7;
    float acc[6] = {0.f, 0.f, 0.f, 0.f, 0.f, 0.f};

    for (int j0 = 0; j0 < 512; j0 += 32) {
        __syncthreads();
        for (int idx = t; idx < 32 * 32; idx += 256) {
            int r = idx >> 5, c4 = idx & 31;
            ((float4*)&zs[r][0])[c4] =
                ((const float4*)&z[(((long)i << 9) + j0 + r) * 128])[c4];
        }
        __syncthreads();
#pragma unroll
        for (int r4 = 0; r4 < 8; r4++) {
            float z0 = zs[r4 * 4 + 0][c];
            float z1 = zs[r4 * 4 + 1][c];
            float z2 = zs[r4 * 4 + 2][c];
            float z3 = zs[r4 * 4 + 3][c];
#pragma unroll
            for (int q = 0; q < 6; q++) {
                float4 s4 = *(const float4*)&sa[hh * 6 + q][j0 + r4 * 4];
                acc[q] += s4.x * z0 + s4.y * z1 + s4.z * z2 + s4.w * z3;
            }
        }
    }
#pragma unroll
    for (int q = 0; q < 6; q++) {
        long idx = (long)i * KCAT + 576 + (hh * 6 + q) * 128 + c;
        split_store(acc[q], &g_cath[idx], &g_catl[idx]);
    }
}

// ---------------- assemble: o copy + inverse-frame o_pt + norms (bf16) ------
__global__ void assemble_kernel(const float* __restrict__ rot, const float* __restrict__ trans) {
    const int i = blockIdx.x;
    const int t = threadIdx.x; // 192
    __shared__ float R[9], T[3];
    if (t < 9) R[t] = rot[i * 9 + t];
    if (t < 3) T[t] = trans[i * 3 + t];
    __syncthreads();

    {
        int h = t >> 4, d = t & 15;
        long idx = (long)i * KCAT + t;
        split_store(g_o1[((long)h * NN + i) * 40 + d], &g_cath[idx], &g_catl[idx]);
    }
    if (t < 96) {
        int h = t >> 3, p = t & 7;
        const float* src = &g_o1[((long)h * NN + i) * 40 + 16 + p * 3];
        float w0 = src[0] - T[0];
        float w1 = src[1] - T[1];
        float w2 = src[2] - T[2];
        float l0 = R[0] * w0 + R[3] * w1 + R[6] * w2;
        float l1 = R[1] * w0 + R[4] * w1 + R[7] * w2;
        float l2 = R[2] * w0 + R[5] * w1 + R[8] * w2;
        long b = (long)i * KCAT;
        split_store(l0, &g_cath[b + 192 + t], &g_catl[b + 192 + t]);
        split_store(l1, &g_cath[b + 288 + t], &g_catl[b + 288 + t]);
        split_store(l2, &g_cath[b + 384 + t], &g_catl[b + 384 + t]);
        float nrm = sqrtf(l0 * l0 + l1 * l1 + l2 * l2 + 1e-8f);
        split_store(nrm, &g_cath[b + 480 + t], &g_catl[b + 480 + t]);
    }
}

// ---------------- stream/event state (lazy init, host-side only) ------------
static cudaStream_t g_s1 = nullptr, g_s2 = nullptr;
static cudaEvent_t g_evRoot, g_evBz, g_evWo, g_evLS, g_evOp, g_evPrep;

// ---------------- launch ----------------------------------------------------
extern "C" void kernel_launch(void* const* d_in, const int* in_sizes, int n_in,
                              void* d_out, int out_size) {
    const float* s     = (const float*)d_in[0];
    const float* z     = (const float*)d_in[1];
    const float* rot   = (const float*)d_in[2];
    const float* trans = (const float*)d_in[3];
    const float* mask  = (const float*)d_in[4];
    const float* Wq    = (const float*)d_in[5];
    const float* bq    = (const float*)d_in[6];
    const float* Wkv   = (const float*)d_in[7];
    const float* bkv   = (const float*)d_in[8];
    const float* Wqp   = (const float*)d_in[9];
    const float* bqp   = (const float*)d_in[10];
    const float* Wkvp  = (const float*)d_in[11];
    const float* bkvp  = (const float*)d_in[12];
    const float* Wb    = (const float*)d_in[13];
    const float* bb    = (const float*)d_in[14];
    const float* head_w= (const float*)d_in[15];
    const float* Wout  = (const float*)d_in[16];
    const float* bout  = (const float*)d_in[17];
    float* out = (float*)d_out;

    if (!g_s1) {
        cudaStreamCreateWithFlags(&g_s1, cudaStreamNonBlocking);
        cudaStreamCreateWithFlags(&g_s2, cudaStreamNonBlocking);
        cudaEventCreateWithFlags(&g_evRoot, cudaEventDisableTiming);
        cudaEventCreateWithFlags(&g_evBz, cudaEventDisableTiming);
        cudaEventCreateWithFlags(&g_evWo, cudaEventDisableTiming);
        cudaEventCreateWithFlags(&g_evLS, cudaEventDisableTiming);
        cudaEventCreateWithFlags(&g_evOp, cudaEventDisableTiming);
        cudaEventCreateWithFlags(&g_evPrep, cudaEventDisableTiming);
    }

    float *pBias, *pProj, *pA, *pVcat, *pO1;
    __nv_bfloat16 *pSh, *pSl, *pWth, *pWtl, *pWoTh, *pWoTl, *pCath, *pCatl;
    cudaGetSymbolAddress((void**)&pBias, g_bias);
    cudaGetSymbolAddress((void**)&pProj, g_proj);
    cudaGetSymbolAddress((void**)&pA, g_a);
    cudaGetSymbolAddress((void**)&pVcat, g_vcat);
    cudaGetSymbolAddress((void**)&pO1, g_o1);
    cudaGetSymbolAddress((void**)&pSh, g_sh);
    cudaGetSymbolAddress((void**)&pSl, g_sl);
    cudaGetSymbolAddress((void**)&pWth, g_Wth);
    cudaGetSymbolAddress((void**)&pWtl, g_Wtl);
    cudaGetSymbolAddress((void**)&pWoTh, g_WoTh);
    cudaGetSymbolAddress((void**)&pWoTl, g_WoTl);
    cudaGetSymbolAddress((void**)&pCath, g_cath);
    cudaGetSymbolAddress((void**)&pCatl, g_catl);

    // fork side streams off the capture (root) stream
    cudaEventRecord(g_evRoot, 0);
    cudaStreamWaitEvent(g_s1, g_evRoot, 0);
    cudaStreamWaitEvent(g_s2, g_evRoot, 0);

    // s1: z-bound bz (independent of projection chain), then WoutT
    bz_kernel<<<512, 256, 0, g_s1>>>(z, Wb, bb);
    cudaEventRecord(g_evBz, g_s1);
    WoutT_kernel<<<dim3(1024 / 32, KCAT / 32), dim3(32, 8), 0, g_s1>>>(Wout);
    cudaEventRecord(g_evWo, g_s1);

    // s2: weight prep (parallel with conv_hl on main)
    packWT_kernel<<<dim3(NPROJ / 32, CS / 32), dim3(32, 8), 0, g_s2>>>(Wq, Wkv, Wqp, Wkvp);
    packbias_kernel<<<(NPROJ + 255) / 256, 256, 0, g_s2>>>(bq, bkv, bqp, bkvp);
    cudaEventRecord(g_evPrep, g_s2);

    // main chain: s conversion -> proj -> pts
    conv_hl_kernel<<<(NN * CS + 255) / 256, 256>>>(s, pSh, pSl, NN * CS);
    cudaStreamWaitEvent(0, g_evPrep, 0);
    hgemm<true><<<dim3(NPROJ / 64, NN / 64), 256>>>(pSh, pSl, pWth, pWtl, pBias, pProj,
                                                    NN, CS, NPROJ);
    pts_kernel<<<512, 384>>>(rot, trans);

    // logits needs bz output
    cudaStreamWaitEvent(0, g_evBz, 0);
    logits_softmax_kernel<<<dim3(64, 12), 256>>>(mask, head_w);
    cudaEventRecord(g_evLS, 0);

    // s2: opair (z-bound) concurrent with attn GEMM + assemble
    cudaStreamWaitEvent(g_s2, g_evLS, 0);
    opair_kernel<<<512, 256, 0, g_s2>>>(z);
    cudaEventRecord(g_evOp, g_s2);

    // main: attention output + assemble
    gemm64<false><<<dim3(1, 8, 12), 256>>>(pA, pVcat, nullptr, pO1, 512, 512, 40,
                                           (long)512 * 512, (long)512 * 40, (long)512 * 40);
    assemble_kernel<<<512, 192>>>(rot, trans);

    // join everything, then final GEMM
    cudaStreamWaitEvent(0, g_evOp, 0);
    cudaStreamWaitEvent(0, g_evWo, 0);
    hgemm<true><<<dim3(1024 / 64, NN / 64), 256>>>(pCath, pCatl, pWoTh, pWoTl, bout, out,
                                                   NN, KCAT, 1024);
}